// round 7
// baseline (speedup 1.0000x reference)
#include <cuda_runtime.h>
#include <cuda_bf16.h>
#include <cstdint>

// ---------------------------------------------------------------------------
// Problem constants
// ---------------------------------------------------------------------------
#define BATCH 2
#define SEQ   2048
#define EMB   2048
#define NH    16
#define NKV   4
#define HD    128
#define WIN   512
#define MROWS (BATCH * SEQ)          // 4096
#define QCOLS (NH * HD)              // 2048
#define KCOLS (NKV * HD)             // 512
#define K3    (3 * EMB)              // 6144  (3-term bf16 split along K)

// ---------------------------------------------------------------------------
// Scratch (static device memory; allocations are forbidden)
// ---------------------------------------------------------------------------
__device__ float g_q[(size_t)MROWS * QCOLS];
__device__ float g_k[(size_t)MROWS * KCOLS];
__device__ float g_v[(size_t)MROWS * KCOLS];

__device__ __nv_bfloat16 g_xs  [(size_t)MROWS * K3];   // [Ah | Al | Ah] of x
__device__ __nv_bfloat16 g_atts[(size_t)MROWS * K3];   // attention out, split
__device__ __nv_bfloat16 g_wqt [(size_t)QCOLS * K3];   // Wq^T split [Bh|Bh|Bl]
__device__ __nv_bfloat16 g_wkt [(size_t)KCOLS * K3];
__device__ __nv_bfloat16 g_wvt [(size_t)KCOLS * K3];
__device__ __nv_bfloat16 g_wot [(size_t)EMB   * K3];   // Wo^T split

// per-(row,head) split arrays for flash attention
__device__ __nv_bfloat16 g_qs3[(size_t)MROWS * NH  * 384];  // [qh|ql|qh]
__device__ __nv_bfloat16 g_ks3[(size_t)MROWS * NKV * 384];  // [kh|kh|kl]
__device__ __nv_bfloat16 g_vs2[(size_t)MROWS * NKV * 256];  // [vh|vl]

// ---------------------------------------------------------------------------
// Helpers
// ---------------------------------------------------------------------------
__device__ __forceinline__ uint32_t smem_to_u32(const void* p) {
    uint32_t a;
    asm("{ .reg .u64 t; cvta.to.shared.u64 t, %1; cvt.u32.u64 %0, t; }" : "=r"(a) : "l"(p));
    return a;
}
#define SWZ128(off) ((off) ^ (((off) >> 3) & 0x70))

__device__ __forceinline__ void cp_async16(uint32_t s, const void* g) {
    asm volatile("cp.async.cg.shared.global [%0], [%1], 16;" :: "r"(s), "l"(g));
}
__device__ __forceinline__ void ldsm_x4(uint32_t* r, uint32_t addr) {
    asm volatile("ldmatrix.sync.aligned.m8n8.x4.shared.b16 {%0,%1,%2,%3}, [%4];"
                 : "=r"(r[0]), "=r"(r[1]), "=r"(r[2]), "=r"(r[3]) : "r"(addr));
}
__device__ __forceinline__ void ldsm_x4_t(uint32_t* r, uint32_t addr) {
    asm volatile("ldmatrix.sync.aligned.m8n8.x4.trans.shared.b16 {%0,%1,%2,%3}, [%4];"
                 : "=r"(r[0]), "=r"(r[1]), "=r"(r[2]), "=r"(r[3]) : "r"(addr));
}
__device__ __forceinline__ void mma16816(float* d, const uint32_t* a, const uint32_t* b) {
    asm volatile("mma.sync.aligned.m16n8k16.row.col.f32.bf16.bf16.f32 "
                 "{%0,%1,%2,%3}, {%4,%5,%6,%7}, {%8,%9}, {%0,%1,%2,%3};"
                 : "+f"(d[0]), "+f"(d[1]), "+f"(d[2]), "+f"(d[3])
                 : "r"(a[0]), "r"(a[1]), "r"(a[2]), "r"(a[3]), "r"(b[0]), "r"(b[1]));
}
__device__ __forceinline__ uint32_t bfpack(__nv_bfloat16 a, __nv_bfloat16 b) {
    __nv_bfloat162 t(a, b);   // .x = a (low, k even), .y = b
    return *reinterpret_cast<uint32_t*>(&t);
}

// ---------------------------------------------------------------------------
// Split kernels
// ---------------------------------------------------------------------------
__global__ void splitrows_kernel(const float* __restrict__ A, __nv_bfloat16* __restrict__ out,
                                 int total) {
    int i = blockIdx.x * 256 + threadIdx.x;
    if (i >= total) return;
    int row = i >> 11;
    int k = i & 2047;
    float v = A[i];
    __nv_bfloat16 hi = __float2bfloat16(v);
    __nv_bfloat16 lo = __float2bfloat16(v - __bfloat162float(hi));
    size_t b = (size_t)row * K3 + k;
    out[b] = hi;
    out[b + EMB] = lo;
    out[b + 2 * EMB] = hi;
}

__global__ void splitw_kernel(const float* __restrict__ W, __nv_bfloat16* __restrict__ out, int N) {
    __shared__ float t[32][33];
    int n0 = blockIdx.x * 32, k0 = blockIdx.y * 32;
    int tx = threadIdx.x, ty = threadIdx.y;
    t[ty][tx] = W[(size_t)(k0 + ty) * N + n0 + tx];
    __syncthreads();
    float v = t[tx][ty];
    __nv_bfloat16 hi = __float2bfloat16(v);
    __nv_bfloat16 lo = __float2bfloat16(v - __bfloat162float(hi));
    size_t b = (size_t)(n0 + ty) * K3 + k0 + tx;
    out[b] = hi;
    out[b + EMB] = hi;
    out[b + 2 * EMB] = lo;
}

// q[4096][2048] -> qs3[(row*NH+h)][384] = [qh | ql | qh]
__global__ void split_q3_kernel(const float* __restrict__ q, __nv_bfloat16* __restrict__ out) {
    int i = blockIdx.x * 256 + threadIdx.x;          // < MROWS*QCOLS
    int brow = i >> 11, c = i & 2047;
    int h = c >> 7, d = c & 127;
    float v = q[i];
    __nv_bfloat16 hi = __float2bfloat16(v);
    __nv_bfloat16 lo = __float2bfloat16(v - __bfloat162float(hi));
    size_t r = ((size_t)brow * NH + h) * 384;
    out[r + d] = hi; out[r + 128 + d] = lo; out[r + 256 + d] = hi;
}

// k[4096][512] -> ks3[(row*NKV+kh)][384] = [kh | kh | kl]
__global__ void split_k3_kernel(const float* __restrict__ k, __nv_bfloat16* __restrict__ out) {
    int i = blockIdx.x * 256 + threadIdx.x;          // < MROWS*KCOLS
    int brow = i >> 9, c = i & 511;
    int kh = c >> 7, d = c & 127;
    float v = k[i];
    __nv_bfloat16 hi = __float2bfloat16(v);
    __nv_bfloat16 lo = __float2bfloat16(v - __bfloat162float(hi));
    size_t r = ((size_t)brow * NKV + kh) * 384;
    out[r + d] = hi; out[r + 128 + d] = hi; out[r + 256 + d] = lo;
}

// v[4096][512] -> vs2[(row*NKV+kh)][256] = [vh | vl]
__global__ void split_v2_kernel(const float* __restrict__ v, __nv_bfloat16* __restrict__ out) {
    int i = blockIdx.x * 256 + threadIdx.x;
    int brow = i >> 9, c = i & 511;
    int kh = c >> 7, d = c & 127;
    float x = v[i];
    __nv_bfloat16 hi = __float2bfloat16(x);
    __nv_bfloat16 lo = __float2bfloat16(x - __bfloat162float(hi));
    size_t r = ((size_t)brow * NKV + kh) * 256;
    out[r + d] = hi; out[r + 128 + d] = lo;
}

// ---------------------------------------------------------------------------
// bf16 mma.sync GEMM (unchanged from R5): C = A'[M,K3] @ Bt'[N,K3]^T
// ---------------------------------------------------------------------------
#define BK_G 64
#define NCHUNK (K3 / BK_G)
#define STAGE_BYTES (2 * 128 * BK_G * 2)
#define NSTAGE 3
#define GEMM_SMEM (NSTAGE * STAGE_BYTES)

__global__ __launch_bounds__(256)
void gemm3bf16_kernel(const __nv_bfloat16* __restrict__ A,
                      const __nv_bfloat16* __restrict__ Bt,
                      float* __restrict__ C, int Ntot) {
    extern __shared__ char smem[];
    const uint32_t sb = smem_to_u32(smem);
    const int tid  = threadIdx.x;
    const int lane = tid & 31;
    const int wid  = tid >> 5;
    const int wm = wid >> 2;
    const int wn = wid & 3;
    const int row0 = blockIdx.y * 128;
    const int col0 = blockIdx.x * 128;

    uint32_t sa[NSTAGE], sbf[NSTAGE];
#pragma unroll
    for (int s = 0; s < NSTAGE; s++) {
        sa[s]  = sb + s * STAGE_BYTES;
        sbf[s] = sb + s * STAGE_BYTES + 16384u;
    }

    float acc[4][4][4];
#pragma unroll
    for (int i = 0; i < 4; i++)
#pragma unroll
        for (int j = 0; j < 4; j++)
#pragma unroll
            for (int r = 0; r < 4; r++) acc[i][j][r] = 0.0f;

    const char* Abase = (const char*)A;
    const char* Bbase = (const char*)Bt;

    auto load_stage = [&](int kc, int s) {
#pragma unroll
        for (int it = 0; it < 8; it++) {
            int seg = tid + it * 256;
            int isA = seg < 1024;
            int s2 = isA ? seg : seg - 1024;
            int r = s2 >> 3, ch = s2 & 7;
            const char* g = (isA ? Abase : Bbase)
                + (size_t)((isA ? row0 : col0) + r) * (K3 * 2) + (size_t)kc * 128 + ch * 16;
            uint32_t saddr = (isA ? sa[s] : sbf[s]) + SWZ128(r * 128 + ch * 16);
            cp_async16(saddr, g);
        }
    };

    load_stage(0, 0);
    asm volatile("cp.async.commit_group;" ::: "memory");
    load_stage(1, 1);
    asm volatile("cp.async.commit_group;" ::: "memory");

    const int sub = lane >> 3;
    const int l7  = lane & 7;

    int sidx = 0;
    for (int c = 0; c < NCHUNK; c++) {
        asm volatile("cp.async.wait_group 1;" ::: "memory");
        __syncthreads();

        if (c + 2 < NCHUNK) {
            int ns = sidx + 2;
            if (ns >= NSTAGE) ns -= NSTAGE;
            load_stage(c + 2, ns);
        }
        asm volatile("cp.async.commit_group;" ::: "memory");

        const uint32_t ab = sa[sidx];
        const uint32_t bb = sbf[sidx];

#pragma unroll
        for (int ks = 0; ks < 4; ks++) {
            uint32_t afr[4][4];
#pragma unroll
            for (int im = 0; im < 4; im++) {
                int r = wm * 64 + im * 16 + (sub & 1) * 8 + l7;
                int cc = ks * 16 + (sub >> 1) * 8;
                ldsm_x4(afr[im], ab + SWZ128(r * 128 + cc * 2));
            }
            uint32_t bfr[2][4];
#pragma unroll
            for (int in2 = 0; in2 < 2; in2++) {
                int r = wn * 32 + in2 * 16 + (sub >> 1) * 8 + l7;
                int cc = ks * 16 + (sub & 1) * 8;
                ldsm_x4(bfr[in2], bb + SWZ128(r * 128 + cc * 2));
            }
#pragma unroll
            for (int im = 0; im < 4; im++)
#pragma unroll
                for (int in = 0; in < 4; in++)
                    mma16816(acc[im][in], afr[im], &bfr[in >> 1][(in & 1) * 2]);
        }

        if (++sidx == NSTAGE) sidx = 0;
    }

    const int gid = lane >> 2;
    const int tig = lane & 3;
#pragma unroll
    for (int im = 0; im < 4; im++) {
#pragma unroll
        for (int in = 0; in < 4; in++) {
            int r = row0 + wm * 64 + im * 16 + gid;
            int cc = col0 + wn * 32 + in * 8 + 2 * tig;
            float2* p0 = (float2*)(C + (size_t)r * Ntot + cc);
            float2* p1 = (float2*)(C + (size_t)(r + 8) * Ntot + cc);
            *p0 = make_float2(acc[im][in][0], acc[im][in][1]);
            *p1 = make_float2(acc[im][in][2], acc[im][in][3]);
        }
    }
}

// ---------------------------------------------------------------------------
// RoPE (rotate-half), in-place; position = row % SEQ.
// ---------------------------------------------------------------------------
__global__ void rope_kernel(float* __restrict__ t, int nh, int total) {
    int idx = blockIdx.x * blockDim.x + threadIdx.x;
    if (idx >= total) return;
    int d = idx & 63;
    int h = (idx >> 6) % nh;
    int row = idx / (64 * nh);
    int pos = row & (SEQ - 1);
    float inv = __expf(-(float)d * (9.210340371976184f / 64.0f));
    float ang = (float)pos * inv;
    float s, c;
    sincosf(ang, &s, &c);
    float* base = t + (size_t)row * (nh * HD) + h * HD;
    float t1 = base[d];
    float t2 = base[d + 64];
    base[d]      = t1 * c - t2 * s;
    base[d + 64] = t1 * s + t2 * c;
}

// ---------------------------------------------------------------------------
// Flash attention: CTA = (qtile 64 positions, head, batch). 4 warps.
// QK^T split bf16 (K'=384), max-free softmax, PV split bf16 (3 terms).
// Writes attention output directly in split [hi|lo|hi] layout to atts.
// smem: Q 48KB + 2 x (K 48KB + V 32KB) = 208KB.
// ---------------------------------------------------------------------------
#define FA_SMEM 212992

__global__ __launch_bounds__(128, 1)
void flash_attn_kernel(const __nv_bfloat16* __restrict__ qs3,
                       const __nv_bfloat16* __restrict__ ks3,
                       const __nv_bfloat16* __restrict__ vs2,
                       __nv_bfloat16* __restrict__ atts) {
    extern __shared__ char smem[];
    const uint32_t sbase = smem_to_u32(smem);
    const int tid = threadIdx.x;
    const int lane = tid & 31;
    const int w = tid >> 5;
    const int sub = lane >> 3, l7 = lane & 7;
    const int gid = lane >> 2, tig = lane & 3;

    const int qt = blockIdx.x;             // 0..31
    const int h  = blockIdx.y;             // 0..15
    const int b  = blockIdx.z;             // 0..1
    const int kh = h >> 2;
    const int i0 = qt * 64;
    const int jt0 = (qt >= 8) ? (qt - 8) : 0;
    const int nt = qt + 1 - jt0;           // 1..9 key tiles
    const int j0 = jt0 * 64;

    const uint32_t QS = sbase;
    const uint32_t KS0 = sbase + 49152u;            // + s*49152
    const uint32_t VS0 = sbase + 147456u;           // + s*32768

    // ---- load Q tile: 64 rows x 384 cols (6 panels of 64 cols/128B) ----
    {
        const char* qb = (const char*)(qs3 + ((size_t)(b * SEQ + i0) * NH + h) * 384);
        for (int idx = tid; idx < 3072; idx += 128) {
            int r = idx / 48, ch = idx % 48;
            cp_async16(QS + (ch >> 3) * 8192 + SWZ128(r * 128 + (ch & 7) * 16),
                       qb + (size_t)r * (NH * 384 * 2) + ch * 16);
        }
    }
    auto load_kv = [&](int t, int s) {
        int jb = j0 + t * 64;
        const char* kb = (const char*)(ks3 + ((size_t)(b * SEQ + jb) * NKV + kh) * 384);
        const char* vb = (const char*)(vs2 + ((size_t)(b * SEQ + jb) * NKV + kh) * 256);
        uint32_t ksb = KS0 + (uint32_t)s * 49152u;
        uint32_t vsb = VS0 + (uint32_t)s * 32768u;
        for (int idx = tid; idx < 5120; idx += 128) {
            if (idx < 3072) {
                int r = idx / 48, ch = idx % 48;
                cp_async16(ksb + (ch >> 3) * 8192 + SWZ128(r * 128 + (ch & 7) * 16),
                           kb + (size_t)r * (NKV * 384 * 2) + ch * 16);
            } else {
                int i2 = idx - 3072;
                int r = i2 / 32, ch = i2 % 32;
                cp_async16(vsb + (ch >> 3) * 8192 + SWZ128(r * 128 + (ch & 7) * 16),
                           vb + (size_t)r * (NKV * 256 * 2) + ch * 16);
            }
        }
    };

    load_kv(0, 0);
    asm volatile("cp.async.commit_group;" ::: "memory");   // group0: Q + K/V tile0
    if (nt > 1) {
        load_kv(1, 1);
        asm volatile("cp.async.commit_group;" ::: "memory");
    }

    float o[16][4];
#pragma unroll
    for (int i = 0; i < 16; i++)
#pragma unroll
        for (int e = 0; e < 4; e++) o[i][e] = 0.0f;
    float l0 = 0.0f, l1 = 0.0f;

    const float SCL2E = 0.08838834764831845f * 1.4426950408889634f;
    const int irow0 = i0 + w * 16 + gid;     // logical query row (d0,d1); +8 for d2,d3

    for (int t = 0; t < nt; t++) {
        if (t + 1 < nt) { asm volatile("cp.async.wait_group 1;" ::: "memory"); }
        else            { asm volatile("cp.async.wait_group 0;" ::: "memory"); }
        __syncthreads();

        const uint32_t ks_ = KS0 + (uint32_t)(t & 1) * 49152u;
        const uint32_t vs_ = VS0 + (uint32_t)(t & 1) * 32768u;

        // ---- scores S = Qtile @ Ktile^T (split, K'=384) ----
        float s[8][4];
#pragma unroll
        for (int nb = 0; nb < 8; nb++)
#pragma unroll
            for (int e = 0; e < 4; e++) s[nb][e] = 0.0f;

#pragma unroll
        for (int t24 = 0; t24 < 24; t24++) {
            int p = t24 >> 2, coff = (t24 & 3) * 16;
            uint32_t af[4];
            ldsm_x4(af, QS + p * 8192 +
                    SWZ128((w * 16 + (sub & 1) * 8 + l7) * 128 + (coff + (sub >> 1) * 8) * 2));
            uint32_t bfr[4][4];
#pragma unroll
            for (int g = 0; g < 4; g++)
                ldsm_x4(bfr[g], ks_ + p * 8192 +
                        SWZ128((g * 16 + (sub >> 1) * 8 + l7) * 128 + (coff + (sub & 1) * 8) * 2));
#pragma unroll
            for (int nb = 0; nb < 8; nb++)
                mma16816(s[nb], af, &bfr[nb >> 1][(nb & 1) * 2]);
        }

        // ---- mask + exp (max-free), accumulate row sums ----
        const int jb = j0 + t * 64;
        float part0 = 0.0f, part1 = 0.0f;
#pragma unroll
        for (int nb = 0; nb < 8; nb++) {
            int jc = jb + nb * 8 + 2 * tig;
#pragma unroll
            for (int e = 0; e < 4; e++) {
                int j = jc + (e & 1);
                int i = irow0 + (e >> 1) * 8;
                bool ok = (j <= i) && (i - j < WIN);
                float p = ok ? exp2f(s[nb][e] * SCL2E) : 0.0f;
                s[nb][e] = p;
            }
            part0 += s[nb][0] + s[nb][1];
            part1 += s[nb][2] + s[nb][3];
        }
        part0 += __shfl_xor_sync(0xffffffffu, part0, 1);
        part0 += __shfl_xor_sync(0xffffffffu, part0, 2);
        part1 += __shfl_xor_sync(0xffffffffu, part1, 1);
        part1 += __shfl_xor_sync(0xffffffffu, part1, 2);
        l0 += part0; l1 += part1;

        // ---- O += P @ Vtile (3-term split) ----
#pragma unroll
        for (int ks2 = 0; ks2 < 4; ks2++) {
            uint32_t ah[4], al[4];
#pragma unroll
            for (int q4 = 0; q4 < 4; q4++) {
                // a0: (row gid, k 2tig..+1) = d0,d1 of nb even ; a1: d2,d3 even;
                // a2: d0,d1 odd ; a3: d2,d3 odd
                int nb = 2 * ks2 + (q4 >> 1);
                int e0 = (q4 & 1) * 2;
                float x = s[nb][e0], y = s[nb][e0 + 1];
                __nv_bfloat16 hx = __float2bfloat16(x), hy = __float2bfloat16(y);
                ah[(q4 >> 1) * 2 + (q4 & 1)] = 0;  // placeholder, fixed below
                (void)hx; (void)hy;
            }
            // explicit build (a0..a3 order)
            {
                float x, y; __nv_bfloat16 hx, hy, lx, ly;
                x = s[2 * ks2][0];     y = s[2 * ks2][1];
                hx = __float2bfloat16(x); hy = __float2bfloat16(y);
                lx = __float2bfloat16(x - __bfloat162float(hx));
                ly = __float2bfloat16(y - __bfloat162float(hy));
                ah[0] = bfpack(hx, hy); al[0] = bfpack(lx, ly);
                x = s[2 * ks2][2];     y = s[2 * ks2][3];
                hx = __float2bfloat16(x); hy = __float2bfloat16(y);
                lx = __float2bfloat16(x - __bfloat162float(hx));
                ly = __float2bfloat16(y - __bfloat162float(hy));
                ah[1] = bfpack(hx, hy); al[1] = bfpack(lx, ly);
                x = s[2 * ks2 + 1][0]; y = s[2 * ks2 + 1][1];
                hx = __float2bfloat16(x); hy = __float2bfloat16(y);
                lx = __float2bfloat16(x - __bfloat162float(hx));
                ly = __float2bfloat16(y - __bfloat162float(hy));
                ah[2] = bfpack(hx, hy); al[2] = bfpack(lx, ly);
                x = s[2 * ks2 + 1][2]; y = s[2 * ks2 + 1][3];
                hx = __float2bfloat16(x); hy = __float2bfloat16(y);
                lx = __float2bfloat16(x - __bfloat162float(hx));
                ly = __float2bfloat16(y - __bfloat162float(hy));
                ah[3] = bfpack(hx, hy); al[3] = bfpack(lx, ly);
            }
#pragma unroll
            for (int g = 0; g < 8; g++) {
                uint32_t bh[4], bl[4];
                uint32_t off = SWZ128((ks2 * 16 + (sub & 1) * 8 + l7) * 128 +
                                      ((g & 3) * 16 + (sub >> 1) * 8) * 2);
                ldsm_x4_t(bh, vs_ + (g >> 2) * 8192 + off);
                ldsm_x4_t(bl, vs_ + 16384u + (g >> 2) * 8192 + off);
                mma16816(o[2 * g],     ah, &bh[0]);
                mma16816(o[2 * g + 1], ah, &bh[2]);
                mma16816(o[2 * g],     al, &bh[0]);
                mma16816(o[2 * g + 1], al, &bh[2]);
                mma16816(o[2 * g],     ah, &bl[0]);
                mma16816(o[2 * g + 1], ah, &bl[2]);
            }
        }

        __syncthreads();
        if (t + 2 < nt) load_kv(t + 2, t & 1);
        asm volatile("cp.async.commit_group;" ::: "memory");
    }

    // ---- normalize + write split output ----
    const float linv0 = 1.0f / l0;
    const float linv1 = 1.0f / l1;
    const size_t row0 = (size_t)(b * SEQ) + irow0;
    const size_t row1 = row0 + 8;
#pragma unroll
    for (int nb = 0; nb < 16; nb++) {
        int c0 = h * 128 + nb * 8 + 2 * tig;
        float v0 = o[nb][0] * linv0, v1 = o[nb][1] * linv0;
        float v2 = o[nb][2] * linv1, v3 = o[nb][3] * linv1;
        __nv_bfloat16 h0 = __float2bfloat16(v0), h1 = __float2bfloat16(v1);
        __nv_bfloat16 h2 = __float2bfloat16(v2), h3 = __float2bfloat16(v3);
        __nv_bfloat16 e0 = __float2bfloat16(v0 - __bfloat162float(h0));
        __nv_bfloat16 e1 = __float2bfloat16(v1 - __bfloat162float(h1));
        __nv_bfloat16 e2 = __float2bfloat16(v2 - __bfloat162float(h2));
        __nv_bfloat16 e3 = __float2bfloat16(v3 - __bfloat162float(h3));
        uint32_t hi01 = bfpack(h0, h1), lo01 = bfpack(e0, e1);
        uint32_t hi23 = bfpack(h2, h3), lo23 = bfpack(e2, e3);
        *(uint32_t*)(atts + row0 * K3 + c0)        = hi01;
        *(uint32_t*)(atts + row0 * K3 + 2048 + c0) = lo01;
        *(uint32_t*)(atts + row0 * K3 + 4096 + c0) = hi01;
        *(uint32_t*)(atts + row1 * K3 + c0)        = hi23;
        *(uint32_t*)(atts + row1 * K3 + 2048 + c0) = lo23;
        *(uint32_t*)(atts + row1 * K3 + 4096 + c0) = hi23;
    }
}

// ---------------------------------------------------------------------------
// Launch
// ---------------------------------------------------------------------------
extern "C" void kernel_launch(void* const* d_in, const int* in_sizes, int n_in,
                              void* d_out, int out_size) {
    const float* x  = (const float*)d_in[0];
    const float* Wq = (const float*)d_in[1];
    const float* Wk = (const float*)d_in[2];
    const float* Wv = (const float*)d_in[3];
    const float* Wo = (const float*)d_in[4];
    float* out = (float*)d_out;

    float *q, *k, *v;
    __nv_bfloat16 *xs, *atts, *wqt, *wkt, *wvt, *wot, *qs3, *ks3, *vs2;
    cudaGetSymbolAddress((void**)&q,    g_q);
    cudaGetSymbolAddress((void**)&k,    g_k);
    cudaGetSymbolAddress((void**)&v,    g_v);
    cudaGetSymbolAddress((void**)&xs,   g_xs);
    cudaGetSymbolAddress((void**)&atts, g_atts);
    cudaGetSymbolAddress((void**)&wqt,  g_wqt);
    cudaGetSymbolAddress((void**)&wkt,  g_wkt);
    cudaGetSymbolAddress((void**)&wvt,  g_wvt);
    cudaGetSymbolAddress((void**)&wot,  g_wot);
    cudaGetSymbolAddress((void**)&qs3,  g_qs3);
    cudaGetSymbolAddress((void**)&ks3,  g_ks3);
    cudaGetSymbolAddress((void**)&vs2,  g_vs2);

    cudaFuncSetAttribute(gemm3bf16_kernel, cudaFuncAttributeMaxDynamicSharedMemorySize, GEMM_SMEM);
    cudaFuncSetAttribute(flash_attn_kernel, cudaFuncAttributeMaxDynamicSharedMemorySize, FA_SMEM);

    // 1) Split inputs/weights into 3-term bf16
    {
        int total = MROWS * EMB;
        splitrows_kernel<<<(total + 255) / 256, 256>>>(x, xs, total);
        dim3 tb(32, 32);
        splitw_kernel<<<dim3(QCOLS / 32, EMB / 32), tb>>>(Wq, wqt, QCOLS);
        splitw_kernel<<<dim3(KCOLS / 32, EMB / 32), tb>>>(Wk, wkt, KCOLS);
        splitw_kernel<<<dim3(KCOLS / 32, EMB / 32), tb>>>(Wv, wvt, KCOLS);
        splitw_kernel<<<dim3(EMB   / 32, QCOLS / 32), tb>>>(Wo, wot, EMB);
    }

    // 2) Projections (tensor cores)
    gemm3bf16_kernel<<<dim3(QCOLS / 128, MROWS / 128), 256, GEMM_SMEM>>>(xs, wqt, q, QCOLS);
    gemm3bf16_kernel<<<dim3(KCOLS / 128, MROWS / 128), 256, GEMM_SMEM>>>(xs, wkt, k, KCOLS);
    gemm3bf16_kernel<<<dim3(KCOLS / 128, MROWS / 128), 256, GEMM_SMEM>>>(xs, wvt, v, KCOLS);

    // 3) RoPE
    {
        int total_q = MROWS * NH * 64;
        rope_kernel<<<(total_q + 255) / 256, 256>>>(q, NH, total_q);
        int total_k = MROWS * NKV * 64;
        rope_kernel<<<(total_k + 255) / 256, 256>>>(k, NKV, total_k);
    }

    // 4) Split q/k/v for flash attention
    split_q3_kernel<<<(MROWS * QCOLS) / 256, 256>>>(q, qs3);
    split_k3_kernel<<<(MROWS * KCOLS) / 256, 256>>>(k, ks3);
    split_v2_kernel<<<(MROWS * KCOLS) / 256, 256>>>(v, vs2);

    // 5) Flash attention (writes split atts directly)
    flash_attn_kernel<<<dim3(SEQ / 64, NH, BATCH), 128, FA_SMEM>>>(qs3, ks3, vs2, atts);

    // 6) Output projection
    gemm3bf16_kernel<<<dim3(EMB / 128, MROWS / 128), 256, GEMM_SMEM>>>(atts, wot, out, EMB);
}

// round 8
// speedup vs baseline: 1.1551x; 1.1551x over previous
#include <cuda_runtime.h>
#include <cuda_bf16.h>
#include <cstdint>

// ---------------------------------------------------------------------------
// Problem constants
// ---------------------------------------------------------------------------
#define BATCH 2
#define SEQ   2048
#define EMB   2048
#define NH    16
#define NKV   4
#define HD    128
#define WIN   512
#define MROWS (BATCH * SEQ)          // 4096
#define QCOLS (NH * HD)              // 2048
#define KCOLS (NKV * HD)             // 512
#define QKVCOLS (QCOLS + 2 * KCOLS)  // 3072
#define K3    (3 * EMB)              // 6144  (3-term bf16 split along K)

// ---------------------------------------------------------------------------
// Scratch (static device memory; allocations are forbidden)
// ---------------------------------------------------------------------------
__device__ float g_qkv[(size_t)MROWS * QKVCOLS];       // fused q|k|v fp32

__device__ __nv_bfloat16 g_xs   [(size_t)MROWS * K3];      // [Ah | Al | Ah] of x
__device__ __nv_bfloat16 g_atts [(size_t)MROWS * K3];      // attention out, split
__device__ __nv_bfloat16 g_wqkvt[(size_t)QKVCOLS * K3];    // [Wq|Wk|Wv]^T split
__device__ __nv_bfloat16 g_wot  [(size_t)EMB * K3];        // Wo^T split

// per-(row,head) split arrays for flash attention
__device__ __nv_bfloat16 g_qs3[(size_t)MROWS * NH  * 384]; // [qh|ql|qh]
__device__ __nv_bfloat16 g_ks3[(size_t)MROWS * NKV * 384]; // [kh|kh|kl]
__device__ __nv_bfloat16 g_vs2[(size_t)MROWS * NKV * 256]; // [vh|vl]

// ---------------------------------------------------------------------------
// Helpers
// ---------------------------------------------------------------------------
__device__ __forceinline__ uint32_t smem_to_u32(const void* p) {
    uint32_t a;
    asm("{ .reg .u64 t; cvta.to.shared.u64 t, %1; cvt.u32.u64 %0, t; }" : "=r"(a) : "l"(p));
    return a;
}
#define SWZ128(off) ((off) ^ (((off) >> 3) & 0x70))

__device__ __forceinline__ void cp_async16(uint32_t s, const void* g) {
    asm volatile("cp.async.cg.shared.global [%0], [%1], 16;" :: "r"(s), "l"(g));
}
__device__ __forceinline__ void ldsm_x4(uint32_t* r, uint32_t addr) {
    asm volatile("ldmatrix.sync.aligned.m8n8.x4.shared.b16 {%0,%1,%2,%3}, [%4];"
                 : "=r"(r[0]), "=r"(r[1]), "=r"(r[2]), "=r"(r[3]) : "r"(addr));
}
__device__ __forceinline__ void ldsm_x4_t(uint32_t* r, uint32_t addr) {
    asm volatile("ldmatrix.sync.aligned.m8n8.x4.trans.shared.b16 {%0,%1,%2,%3}, [%4];"
                 : "=r"(r[0]), "=r"(r[1]), "=r"(r[2]), "=r"(r[3]) : "r"(addr));
}
__device__ __forceinline__ void mma16816(float* d, const uint32_t* a, const uint32_t* b) {
    asm volatile("mma.sync.aligned.m16n8k16.row.col.f32.bf16.bf16.f32 "
                 "{%0,%1,%2,%3}, {%4,%5,%6,%7}, {%8,%9}, {%0,%1,%2,%3};"
                 : "+f"(d[0]), "+f"(d[1]), "+f"(d[2]), "+f"(d[3])
                 : "r"(a[0]), "r"(a[1]), "r"(a[2]), "r"(a[3]), "r"(b[0]), "r"(b[1]));
}
__device__ __forceinline__ uint32_t bfpack(__nv_bfloat16 a, __nv_bfloat16 b) {
    __nv_bfloat162 t(a, b);
    return *reinterpret_cast<uint32_t*>(&t);
}

// ---------------------------------------------------------------------------
// Split kernels
// ---------------------------------------------------------------------------
__global__ void splitrows_kernel(const float* __restrict__ A, __nv_bfloat16* __restrict__ out,
                                 int total) {
    int i = blockIdx.x * 256 + threadIdx.x;
    if (i >= total) return;
    int row = i >> 11;
    int k = i & 2047;
    float v = A[i];
    __nv_bfloat16 hi = __float2bfloat16(v);
    __nv_bfloat16 lo = __float2bfloat16(v - __bfloat162float(hi));
    size_t b = (size_t)row * K3 + k;
    out[b] = hi;
    out[b + EMB] = lo;
    out[b + 2 * EMB] = hi;
}

__global__ void splitw_kernel(const float* __restrict__ W, __nv_bfloat16* __restrict__ out, int N) {
    __shared__ float t[32][33];
    int n0 = blockIdx.x * 32, k0 = blockIdx.y * 32;
    int tx = threadIdx.x, ty = threadIdx.y;
    t[ty][tx] = W[(size_t)(k0 + ty) * N + n0 + tx];
    __syncthreads();
    float v = t[tx][ty];
    __nv_bfloat16 hi = __float2bfloat16(v);
    __nv_bfloat16 lo = __float2bfloat16(v - __bfloat162float(hi));
    size_t b = (size_t)(n0 + ty) * K3 + k0 + tx;
    out[b] = hi;
    out[b + EMB] = hi;
    out[b + 2 * EMB] = lo;
}

// qkv[row][h*128 + d] -> rope -> qs3[(row*NH+h)][384] = [qh | ql | qh]
// one thread per (row, h, d<64) rotation pair
__global__ void rope_split_q_kernel(const float* __restrict__ qkv, __nv_bfloat16* __restrict__ out) {
    int idx = blockIdx.x * 256 + threadIdx.x;        // < MROWS*NH*64
    int d = idx & 63;
    int h = (idx >> 6) & (NH - 1);
    int row = idx >> 10;
    int pos = row & (SEQ - 1);
    float inv = __expf(-(float)d * (9.210340371976184f / 64.0f));
    float ang = (float)pos * inv;
    float sn, cs;
    sincosf(ang, &sn, &cs);
    const float* base = qkv + (size_t)row * QKVCOLS + h * HD;
    float t1 = base[d], t2 = base[d + 64];
    float v0 = t1 * cs - t2 * sn;
    float v1 = t1 * sn + t2 * cs;
    __nv_bfloat16 h0 = __float2bfloat16(v0), h1 = __float2bfloat16(v1);
    __nv_bfloat16 l0 = __float2bfloat16(v0 - __bfloat162float(h0));
    __nv_bfloat16 l1 = __float2bfloat16(v1 - __bfloat162float(h1));
    size_t r = ((size_t)row * NH + h) * 384;
    out[r + d] = h0;       out[r + d + 64] = h1;
    out[r + 128 + d] = l0; out[r + 192 + d] = l1;
    out[r + 256 + d] = h0; out[r + 320 + d] = h1;
}

// qkv[row][2048 + kh*128 + d] -> rope -> ks3[(row*NKV+kh)][384] = [kh | kh | kl]
__global__ void rope_split_k_kernel(const float* __restrict__ qkv, __nv_bfloat16* __restrict__ out) {
    int idx = blockIdx.x * 256 + threadIdx.x;        // < MROWS*NKV*64
    int d = idx & 63;
    int kh = (idx >> 6) & (NKV - 1);
    int row = idx >> 8;
    int pos = row & (SEQ - 1);
    float inv = __expf(-(float)d * (9.210340371976184f / 64.0f));
    float ang = (float)pos * inv;
    float sn, cs;
    sincosf(ang, &sn, &cs);
    const float* base = qkv + (size_t)row * QKVCOLS + QCOLS + kh * HD;
    float t1 = base[d], t2 = base[d + 64];
    float v0 = t1 * cs - t2 * sn;
    float v1 = t1 * sn + t2 * cs;
    __nv_bfloat16 h0 = __float2bfloat16(v0), h1 = __float2bfloat16(v1);
    __nv_bfloat16 l0 = __float2bfloat16(v0 - __bfloat162float(h0));
    __nv_bfloat16 l1 = __float2bfloat16(v1 - __bfloat162float(h1));
    size_t r = ((size_t)row * NKV + kh) * 384;
    out[r + d] = h0;       out[r + d + 64] = h1;
    out[r + 128 + d] = h0; out[r + 192 + d] = h1;
    out[r + 256 + d] = l0; out[r + 320 + d] = l1;
}

// qkv[row][2560 + kh*128 + d] -> vs2[(row*NKV+kh)][256] = [vh | vl]
__global__ void split_v2_kernel(const float* __restrict__ qkv, __nv_bfloat16* __restrict__ out) {
    int i = blockIdx.x * 256 + threadIdx.x;          // < MROWS*KCOLS
    int c = i & 511, brow = i >> 9;
    int kh = c >> 7, d = c & 127;
    float x = qkv[(size_t)brow * QKVCOLS + QCOLS + KCOLS + kh * HD + d];
    __nv_bfloat16 hi = __float2bfloat16(x);
    __nv_bfloat16 lo = __float2bfloat16(x - __bfloat162float(hi));
    size_t r = ((size_t)brow * NKV + kh) * 256;
    out[r + d] = hi; out[r + 128 + d] = lo;
}

// ---------------------------------------------------------------------------
// bf16 mma.sync GEMM: C[M, Ntot] = A'[M, K3] @ Bt'[Ntot, K3]^T
// CTA 128x256, BK=64, 8 warps (2x4), warp tile 64x64.
// 3-stage cp.async pipeline, one barrier per chunk.
// ---------------------------------------------------------------------------
#define BK_G 64
#define NCHUNK (K3 / BK_G)                 // 96
#define ASTG (128 * BK_G * 2)              // 16384
#define BSTG (256 * BK_G * 2)              // 32768
#define STAGE_BYTES (ASTG + BSTG)          // 49152
#define NSTAGE 3
#define GEMM_SMEM (NSTAGE * STAGE_BYTES)   // 147456

__global__ __launch_bounds__(256, 1)
void gemm3bf16_kernel(const __nv_bfloat16* __restrict__ A,
                      const __nv_bfloat16* __restrict__ Bt,
                      float* __restrict__ C, int Ntot) {
    extern __shared__ char smem[];
    const uint32_t sb = smem_to_u32(smem);
    const int tid  = threadIdx.x;
    const int lane = tid & 31;
    const int wid  = tid >> 5;
    const int wm = wid >> 2;                // 0..1 -> M offset 64*wm
    const int wn = wid & 3;                 // 0..3 -> N offset 64*wn
    const int row0 = blockIdx.y * 128;
    const int col0 = blockIdx.x * 256;

    uint32_t sa[NSTAGE], sbf[NSTAGE];
#pragma unroll
    for (int s = 0; s < NSTAGE; s++) {
        sa[s]  = sb + s * STAGE_BYTES;
        sbf[s] = sb + s * STAGE_BYTES + ASTG;
    }

    float acc[4][8][4];
#pragma unroll
    for (int i = 0; i < 4; i++)
#pragma unroll
        for (int j = 0; j < 8; j++)
#pragma unroll
            for (int r = 0; r < 4; r++) acc[i][j][r] = 0.0f;

    const char* Abase = (const char*)A;
    const char* Bbase = (const char*)Bt;

    // stage loader: chunk kc -> buffer s. 3072 segs of 16B, 12 per thread.
    auto load_stage = [&](int kc, int s) {
#pragma unroll
        for (int it = 0; it < 12; it++) {
            int seg = tid + it * 256;               // 0..3071
            int isA = seg < 1024;
            int s2 = isA ? seg : seg - 1024;
            int r = s2 >> 3, ch = s2 & 7;
            const char* g = (isA ? Abase : Bbase)
                + (size_t)((isA ? row0 : col0) + r) * (K3 * 2) + (size_t)kc * 128 + ch * 16;
            uint32_t saddr = (isA ? sa[s] : sbf[s]) + SWZ128(r * 128 + ch * 16);
            cp_async16(saddr, g);
        }
    };

    load_stage(0, 0);
    asm volatile("cp.async.commit_group;" ::: "memory");
    load_stage(1, 1);
    asm volatile("cp.async.commit_group;" ::: "memory");

    const int sub = lane >> 3;
    const int l7  = lane & 7;

    int sidx = 0;
    for (int c = 0; c < NCHUNK; c++) {
        asm volatile("cp.async.wait_group 1;" ::: "memory");
        __syncthreads();

        if (c + 2 < NCHUNK) {
            int ns = sidx + 2;
            if (ns >= NSTAGE) ns -= NSTAGE;
            load_stage(c + 2, ns);
        }
        asm volatile("cp.async.commit_group;" ::: "memory");

        const uint32_t ab = sa[sidx];
        const uint32_t bb = sbf[sidx];

#pragma unroll
        for (int ks = 0; ks < 4; ks++) {
            uint32_t afr[4][4];
#pragma unroll
            for (int im = 0; im < 4; im++) {
                int r = wm * 64 + im * 16 + (sub & 1) * 8 + l7;
                int cc = ks * 16 + (sub >> 1) * 8;
                ldsm_x4(afr[im], ab + SWZ128(r * 128 + cc * 2));
            }
            uint32_t bfr[4][4];
#pragma unroll
            for (int g = 0; g < 4; g++) {
                int r = wn * 64 + g * 16 + (sub >> 1) * 8 + l7;   // n index
                int cc = ks * 16 + (sub & 1) * 8;                 // k index
                ldsm_x4(bfr[g], bb + SWZ128(r * 128 + cc * 2));
            }
#pragma unroll
            for (int im = 0; im < 4; im++)
#pragma unroll
                for (int in = 0; in < 8; in++)
                    mma16816(acc[im][in], afr[im], &bfr[in >> 1][(in & 1) * 2]);
        }

        if (++sidx == NSTAGE) sidx = 0;
    }

    const int gid = lane >> 2;
    const int tig = lane & 3;
#pragma unroll
    for (int im = 0; im < 4; im++) {
#pragma unroll
        for (int in = 0; in < 8; in++) {
            int r = row0 + wm * 64 + im * 16 + gid;
            int cc = col0 + wn * 64 + in * 8 + 2 * tig;
            float2* p0 = (float2*)(C + (size_t)r * Ntot + cc);
            float2* p1 = (float2*)(C + (size_t)(r + 8) * Ntot + cc);
            *p0 = make_float2(acc[im][in][0], acc[im][in][1]);
            *p1 = make_float2(acc[im][in][2], acc[im][in][3]);
        }
    }
}

// ---------------------------------------------------------------------------
// Flash attention (unchanged from R7): CTA = (qtile 64, head, batch), 4 warps.
// ---------------------------------------------------------------------------
#define FA_SMEM 212992

__global__ __launch_bounds__(128, 1)
void flash_attn_kernel(const __nv_bfloat16* __restrict__ qs3,
                       const __nv_bfloat16* __restrict__ ks3,
                       const __nv_bfloat16* __restrict__ vs2,
                       __nv_bfloat16* __restrict__ atts) {
    extern __shared__ char smem[];
    const uint32_t sbase = smem_to_u32(smem);
    const int tid = threadIdx.x;
    const int lane = tid & 31;
    const int w = tid >> 5;
    const int sub = lane >> 3, l7 = lane & 7;
    const int gid = lane >> 2, tig = lane & 3;

    const int qt = blockIdx.x;
    const int h  = blockIdx.y;
    const int b  = blockIdx.z;
    const int kh = h >> 2;
    const int i0 = qt * 64;
    const int jt0 = (qt >= 8) ? (qt - 8) : 0;
    const int nt = qt + 1 - jt0;
    const int j0 = jt0 * 64;

    const uint32_t QS = sbase;
    const uint32_t KS0 = sbase + 49152u;
    const uint32_t VS0 = sbase + 147456u;

    {
        const char* qb = (const char*)(qs3 + ((size_t)(b * SEQ + i0) * NH + h) * 384);
        for (int idx = tid; idx < 3072; idx += 128) {
            int r = idx / 48, ch = idx % 48;
            cp_async16(QS + (ch >> 3) * 8192 + SWZ128(r * 128 + (ch & 7) * 16),
                       qb + (size_t)r * (NH * 384 * 2) + ch * 16);
        }
    }
    auto load_kv = [&](int t, int s) {
        int jb = j0 + t * 64;
        const char* kb = (const char*)(ks3 + ((size_t)(b * SEQ + jb) * NKV + kh) * 384);
        const char* vb = (const char*)(vs2 + ((size_t)(b * SEQ + jb) * NKV + kh) * 256);
        uint32_t ksb = KS0 + (uint32_t)s * 49152u;
        uint32_t vsb = VS0 + (uint32_t)s * 32768u;
        for (int idx = tid; idx < 5120; idx += 128) {
            if (idx < 3072) {
                int r = idx / 48, ch = idx % 48;
                cp_async16(ksb + (ch >> 3) * 8192 + SWZ128(r * 128 + (ch & 7) * 16),
                           kb + (size_t)r * (NKV * 384 * 2) + ch * 16);
            } else {
                int i2 = idx - 3072;
                int r = i2 / 32, ch = i2 % 32;
                cp_async16(vsb + (ch >> 3) * 8192 + SWZ128(r * 128 + (ch & 7) * 16),
                           vb + (size_t)r * (NKV * 256 * 2) + ch * 16);
            }
        }
    };

    load_kv(0, 0);
    asm volatile("cp.async.commit_group;" ::: "memory");
    if (nt > 1) {
        load_kv(1, 1);
        asm volatile("cp.async.commit_group;" ::: "memory");
    }

    float o[16][4];
#pragma unroll
    for (int i = 0; i < 16; i++)
#pragma unroll
        for (int e = 0; e < 4; e++) o[i][e] = 0.0f;
    float l0 = 0.0f, l1 = 0.0f;

    const float SCL2E = 0.08838834764831845f * 1.4426950408889634f;
    const int irow0 = i0 + w * 16 + gid;

    for (int t = 0; t < nt; t++) {
        if (t + 1 < nt) { asm volatile("cp.async.wait_group 1;" ::: "memory"); }
        else            { asm volatile("cp.async.wait_group 0;" ::: "memory"); }
        __syncthreads();

        const uint32_t ks_ = KS0 + (uint32_t)(t & 1) * 49152u;
        const uint32_t vs_ = VS0 + (uint32_t)(t & 1) * 32768u;

        float s[8][4];
#pragma unroll
        for (int nb = 0; nb < 8; nb++)
#pragma unroll
            for (int e = 0; e < 4; e++) s[nb][e] = 0.0f;

#pragma unroll
        for (int t24 = 0; t24 < 24; t24++) {
            int p = t24 >> 2, coff = (t24 & 3) * 16;
            uint32_t af[4];
            ldsm_x4(af, QS + p * 8192 +
                    SWZ128((w * 16 + (sub & 1) * 8 + l7) * 128 + (coff + (sub >> 1) * 8) * 2));
            uint32_t bfr[4][4];
#pragma unroll
            for (int g = 0; g < 4; g++)
                ldsm_x4(bfr[g], ks_ + p * 8192 +
                        SWZ128((g * 16 + (sub >> 1) * 8 + l7) * 128 + (coff + (sub & 1) * 8) * 2));
#pragma unroll
            for (int nb = 0; nb < 8; nb++)
                mma16816(s[nb], af, &bfr[nb >> 1][(nb & 1) * 2]);
        }

        const int jb = j0 + t * 64;
        float part0 = 0.0f, part1 = 0.0f;
#pragma unroll
        for (int nb = 0; nb < 8; nb++) {
            int jc = jb + nb * 8 + 2 * tig;
#pragma unroll
            for (int e = 0; e < 4; e++) {
                int j = jc + (e & 1);
                int i = irow0 + (e >> 1) * 8;
                bool ok = (j <= i) && (i - j < WIN);
                float p = ok ? exp2f(s[nb][e] * SCL2E) : 0.0f;
                s[nb][e] = p;
            }
            part0 += s[nb][0] + s[nb][1];
            part1 += s[nb][2] + s[nb][3];
        }
        part0 += __shfl_xor_sync(0xffffffffu, part0, 1);
        part0 += __shfl_xor_sync(0xffffffffu, part0, 2);
        part1 += __shfl_xor_sync(0xffffffffu, part1, 1);
        part1 += __shfl_xor_sync(0xffffffffu, part1, 2);
        l0 += part0; l1 += part1;

#pragma unroll
        for (int ks2 = 0; ks2 < 4; ks2++) {
            uint32_t ah[4], al[4];
            {
                float x, y; __nv_bfloat16 hx, hy, lx, ly;
                x = s[2 * ks2][0];     y = s[2 * ks2][1];
                hx = __float2bfloat16(x); hy = __float2bfloat16(y);
                lx = __float2bfloat16(x - __bfloat162float(hx));
                ly = __float2bfloat16(y - __bfloat162float(hy));
                ah[0] = bfpack(hx, hy); al[0] = bfpack(lx, ly);
                x = s[2 * ks2][2];     y = s[2 * ks2][3];
                hx = __float2bfloat16(x); hy = __float2bfloat16(y);
                lx = __float2bfloat16(x - __bfloat162float(hx));
                ly = __float2bfloat16(y - __bfloat162float(hy));
                ah[1] = bfpack(hx, hy); al[1] = bfpack(lx, ly);
                x = s[2 * ks2 + 1][0]; y = s[2 * ks2 + 1][1];
                hx = __float2bfloat16(x); hy = __float2bfloat16(y);
                lx = __float2bfloat16(x - __bfloat162float(hx));
                ly = __float2bfloat16(y - __bfloat162float(hy));
                ah[2] = bfpack(hx, hy); al[2] = bfpack(lx, ly);
                x = s[2 * ks2 + 1][2]; y = s[2 * ks2 + 1][3];
                hx = __float2bfloat16(x); hy = __float2bfloat16(y);
                lx = __float2bfloat16(x - __bfloat162float(hx));
                ly = __float2bfloat16(y - __bfloat162float(hy));
                ah[3] = bfpack(hx, hy); al[3] = bfpack(lx, ly);
            }
#pragma unroll
            for (int g = 0; g < 8; g++) {
                uint32_t bh[4], bl[4];
                uint32_t off = SWZ128((ks2 * 16 + (sub & 1) * 8 + l7) * 128 +
                                      ((g & 3) * 16 + (sub >> 1) * 8) * 2);
                ldsm_x4_t(bh, vs_ + (g >> 2) * 8192 + off);
                ldsm_x4_t(bl, vs_ + 16384u + (g >> 2) * 8192 + off);
                mma16816(o[2 * g],     ah, &bh[0]);
                mma16816(o[2 * g + 1], ah, &bh[2]);
                mma16816(o[2 * g],     al, &bh[0]);
                mma16816(o[2 * g + 1], al, &bh[2]);
                mma16816(o[2 * g],     ah, &bl[0]);
                mma16816(o[2 * g + 1], ah, &bl[2]);
            }
        }

        __syncthreads();
        if (t + 2 < nt) load_kv(t + 2, t & 1);
        asm volatile("cp.async.commit_group;" ::: "memory");
    }

    const float linv0 = 1.0f / l0;
    const float linv1 = 1.0f / l1;
    const size_t row0 = (size_t)(b * SEQ) + irow0;
    const size_t row1 = row0 + 8;
#pragma unroll
    for (int nb = 0; nb < 16; nb++) {
        int c0 = h * 128 + nb * 8 + 2 * tig;
        float v0 = o[nb][0] * linv0, v1 = o[nb][1] * linv0;
        float v2 = o[nb][2] * linv1, v3 = o[nb][3] * linv1;
        __nv_bfloat16 h0 = __float2bfloat16(v0), h1 = __float2bfloat16(v1);
        __nv_bfloat16 h2 = __float2bfloat16(v2), h3 = __float2bfloat16(v3);
        __nv_bfloat16 e0 = __float2bfloat16(v0 - __bfloat162float(h0));
        __nv_bfloat16 e1 = __float2bfloat16(v1 - __bfloat162float(h1));
        __nv_bfloat16 e2 = __float2bfloat16(v2 - __bfloat162float(h2));
        __nv_bfloat16 e3 = __float2bfloat16(v3 - __bfloat162float(h3));
        uint32_t hi01 = bfpack(h0, h1), lo01 = bfpack(e0, e1);
        uint32_t hi23 = bfpack(h2, h3), lo23 = bfpack(e2, e3);
        *(uint32_t*)(atts + row0 * K3 + c0)        = hi01;
        *(uint32_t*)(atts + row0 * K3 + 2048 + c0) = lo01;
        *(uint32_t*)(atts + row0 * K3 + 4096 + c0) = hi01;
        *(uint32_t*)(atts + row1 * K3 + c0)        = hi23;
        *(uint32_t*)(atts + row1 * K3 + 2048 + c0) = lo23;
        *(uint32_t*)(atts + row1 * K3 + 4096 + c0) = hi23;
    }
}

// ---------------------------------------------------------------------------
// Launch
// ---------------------------------------------------------------------------
extern "C" void kernel_launch(void* const* d_in, const int* in_sizes, int n_in,
                              void* d_out, int out_size) {
    const float* x  = (const float*)d_in[0];
    const float* Wq = (const float*)d_in[1];
    const float* Wk = (const float*)d_in[2];
    const float* Wv = (const float*)d_in[3];
    const float* Wo = (const float*)d_in[4];
    float* out = (float*)d_out;

    float *qkv;
    __nv_bfloat16 *xs, *atts, *wqkvt, *wot, *qs3, *ks3, *vs2;
    cudaGetSymbolAddress((void**)&qkv,   g_qkv);
    cudaGetSymbolAddress((void**)&xs,    g_xs);
    cudaGetSymbolAddress((void**)&atts,  g_atts);
    cudaGetSymbolAddress((void**)&wqkvt, g_wqkvt);
    cudaGetSymbolAddress((void**)&wot,   g_wot);
    cudaGetSymbolAddress((void**)&qs3,   g_qs3);
    cudaGetSymbolAddress((void**)&ks3,   g_ks3);
    cudaGetSymbolAddress((void**)&vs2,   g_vs2);

    cudaFuncSetAttribute(gemm3bf16_kernel, cudaFuncAttributeMaxDynamicSharedMemorySize, GEMM_SMEM);
    cudaFuncSetAttribute(flash_attn_kernel, cudaFuncAttributeMaxDynamicSharedMemorySize, FA_SMEM);

    // 1) Split inputs/weights into 3-term bf16 ([Wq|Wk|Wv]^T fused)
    {
        int total = MROWS * EMB;
        splitrows_kernel<<<(total + 255) / 256, 256>>>(x, xs, total);
        dim3 tb(32, 32);
        splitw_kernel<<<dim3(QCOLS / 32, EMB / 32), tb>>>(Wq, wqkvt, QCOLS);
        splitw_kernel<<<dim3(KCOLS / 32, EMB / 32), tb>>>(Wk, wqkvt + (size_t)QCOLS * K3, KCOLS);
        splitw_kernel<<<dim3(KCOLS / 32, EMB / 32), tb>>>(Wv, wqkvt + (size_t)(QCOLS + KCOLS) * K3, KCOLS);
        splitw_kernel<<<dim3(EMB / 32, QCOLS / 32), tb>>>(Wo, wot, EMB);
    }

    // 2) Fused QKV projection (tensor cores), C = [q|k|v] fp32
    gemm3bf16_kernel<<<dim3(QKVCOLS / 256, MROWS / 128), 256, GEMM_SMEM>>>(xs, wqkvt, qkv, QKVCOLS);

    // 3) Fused RoPE + split into flash-attention layouts
    rope_split_q_kernel<<<(MROWS * NH * 64) / 256, 256>>>(qkv, qs3);
    rope_split_k_kernel<<<(MROWS * NKV * 64) / 256, 256>>>(qkv, ks3);
    split_v2_kernel<<<(MROWS * KCOLS) / 256, 256>>>(qkv, vs2);

    // 4) Flash attention (writes split atts directly)
    flash_attn_kernel<<<dim3(SEQ / 64, NH, BATCH), 128, FA_SMEM>>>(qs3, ks3, vs2, atts);

    // 5) Output projection
    gemm3bf16_kernel<<<dim3(EMB / 256, MROWS / 128), 256, GEMM_SMEM>>>(atts, wot, out, EMB);
}

// round 12
// speedup vs baseline: 1.2587x; 1.0897x over previous
#include <cuda_runtime.h>
#include <cuda_bf16.h>
#include <cstdint>

// ---------------------------------------------------------------------------
// Problem constants
// ---------------------------------------------------------------------------
#define BATCH 2
#define SEQ   2048
#define EMB   2048
#define NH    16
#define NKV   4
#define HD    128
#define WIN   512
#define MROWS (BATCH * SEQ)          // 4096
#define QCOLS (NH * HD)              // 2048
#define KCOLS (NKV * HD)             // 512
#define QKVCOLS (QCOLS + 2 * KCOLS)  // 3072
#define K3    (3 * EMB)              // 6144  (3-term bf16 split along K)

// ---------------------------------------------------------------------------
// Scratch (static device memory; allocations are forbidden)
// ---------------------------------------------------------------------------
__device__ float g_qkv[(size_t)MROWS * QKVCOLS];       // fused q|k|v fp32

__device__ __nv_bfloat16 g_xs   [(size_t)MROWS * K3];      // [Ah | Al | Ah] of x
__device__ __nv_bfloat16 g_atts [(size_t)MROWS * K3];      // attention out, split
__device__ __nv_bfloat16 g_wqkvt[(size_t)QKVCOLS * K3];    // [Wq|Wk|Wv]^T split
__device__ __nv_bfloat16 g_wot  [(size_t)EMB * K3];        // Wo^T split

// per-(row,head) split arrays for flash attention
__device__ __nv_bfloat16 g_qs2[(size_t)MROWS * NH  * 256]; // [qh|ql]
__device__ __nv_bfloat16 g_ks2[(size_t)MROWS * NKV * 256]; // [kh|kl]
__device__ __nv_bfloat16 g_vs2[(size_t)MROWS * NKV * 256]; // [vh|vl]

// ---------------------------------------------------------------------------
// Helpers
// ---------------------------------------------------------------------------
__device__ __forceinline__ uint32_t smem_to_u32(const void* p) {
    uint32_t a;
    asm("{ .reg .u64 t; cvta.to.shared.u64 t, %1; cvt.u32.u64 %0, t; }" : "=r"(a) : "l"(p));
    return a;
}
#define SWZ128(off) ((off) ^ (((off) >> 3) & 0x70))

__device__ __forceinline__ void cp_async16(uint32_t s, const void* g) {
    asm volatile("cp.async.cg.shared.global [%0], [%1], 16;" :: "r"(s), "l"(g));
}
__device__ __forceinline__ void ldsm_x4(uint32_t* r, uint32_t addr) {
    asm volatile("ldmatrix.sync.aligned.m8n8.x4.shared.b16 {%0,%1,%2,%3}, [%4];"
                 : "=r"(r[0]), "=r"(r[1]), "=r"(r[2]), "=r"(r[3]) : "r"(addr));
}
__device__ __forceinline__ void ldsm_x4_t(uint32_t* r, uint32_t addr) {
    asm volatile("ldmatrix.sync.aligned.m8n8.x4.trans.shared.b16 {%0,%1,%2,%3}, [%4];"
                 : "=r"(r[0]), "=r"(r[1]), "=r"(r[2]), "=r"(r[3]) : "r"(addr));
}
__device__ __forceinline__ void mma16816(float* d, const uint32_t* a, const uint32_t* b) {
    asm volatile("mma.sync.aligned.m16n8k16.row.col.f32.bf16.bf16.f32 "
                 "{%0,%1,%2,%3}, {%4,%5,%6,%7}, {%8,%9}, {%0,%1,%2,%3};"
                 : "+f"(d[0]), "+f"(d[1]), "+f"(d[2]), "+f"(d[3])
                 : "r"(a[0]), "r"(a[1]), "r"(a[2]), "r"(a[3]), "r"(b[0]), "r"(b[1]));
}
__device__ __forceinline__ uint32_t bfpack(__nv_bfloat16 a, __nv_bfloat16 b) {
    __nv_bfloat162 t(a, b);
    return *reinterpret_cast<uint32_t*>(&t);
}

// ---------------------------------------------------------------------------
// Split kernels
// ---------------------------------------------------------------------------
__global__ void splitrows_kernel(const float* __restrict__ A, __nv_bfloat16* __restrict__ out,
                                 int total) {
    int i = blockIdx.x * 256 + threadIdx.x;
    if (i >= total) return;
    int row = i >> 11;
    int k = i & 2047;
    float v = A[i];
    __nv_bfloat16 hi = __float2bfloat16(v);
    __nv_bfloat16 lo = __float2bfloat16(v - __bfloat162float(hi));
    size_t b = (size_t)row * K3 + k;
    out[b] = hi;
    out[b + EMB] = lo;
    out[b + 2 * EMB] = hi;
}

__global__ void splitw_kernel(const float* __restrict__ W, __nv_bfloat16* __restrict__ out, int N) {
    __shared__ float t[32][33];
    int n0 = blockIdx.x * 32, k0 = blockIdx.y * 32;
    int tx = threadIdx.x, ty = threadIdx.y;
    t[ty][tx] = W[(size_t)(k0 + ty) * N + n0 + tx];
    __syncthreads();
    float v = t[tx][ty];
    __nv_bfloat16 hi = __float2bfloat16(v);
    __nv_bfloat16 lo = __float2bfloat16(v - __bfloat162float(hi));
    size_t b = (size_t)(n0 + ty) * K3 + k0 + tx;
    out[b] = hi;
    out[b + EMB] = hi;
    out[b + 2 * EMB] = lo;
}

// qkv[row][h*128 + d] -> rope -> qs2[(row*NH+h)][256] = [qh | ql]
__global__ void rope_split_q_kernel(const float* __restrict__ qkv, __nv_bfloat16* __restrict__ out) {
    int idx = blockIdx.x * 256 + threadIdx.x;        // < MROWS*NH*64
    int d = idx & 63;
    int h = (idx >> 6) & (NH - 1);
    int row = idx >> 10;
    int pos = row & (SEQ - 1);
    float inv = __expf(-(float)d * (9.210340371976184f / 64.0f));
    float ang = (float)pos * inv;
    float sn, cs;
    sincosf(ang, &sn, &cs);
    const float* base = qkv + (size_t)row * QKVCOLS + h * HD;
    float t1 = base[d], t2 = base[d + 64];
    float v0 = t1 * cs - t2 * sn;
    float v1 = t1 * sn + t2 * cs;
    __nv_bfloat16 h0 = __float2bfloat16(v0), h1 = __float2bfloat16(v1);
    __nv_bfloat16 l0 = __float2bfloat16(v0 - __bfloat162float(h0));
    __nv_bfloat16 l1 = __float2bfloat16(v1 - __bfloat162float(h1));
    size_t r = ((size_t)row * NH + h) * 256;
    out[r + d] = h0;       out[r + d + 64] = h1;
    out[r + 128 + d] = l0; out[r + 192 + d] = l1;
}

// qkv[row][2048 + kh*128 + d] -> rope -> ks2[(row*NKV+kh)][256] = [kh | kl]
__global__ void rope_split_k_kernel(const float* __restrict__ qkv, __nv_bfloat16* __restrict__ out) {
    int idx = blockIdx.x * 256 + threadIdx.x;        // < MROWS*NKV*64
    int d = idx & 63;
    int kh = (idx >> 6) & (NKV - 1);
    int row = idx >> 8;
    int pos = row & (SEQ - 1);
    float inv = __expf(-(float)d * (9.210340371976184f / 64.0f));
    float ang = (float)pos * inv;
    float sn, cs;
    sincosf(ang, &sn, &cs);
    const float* base = qkv + (size_t)row * QKVCOLS + QCOLS + kh * HD;
    float t1 = base[d], t2 = base[d + 64];
    float v0 = t1 * cs - t2 * sn;
    float v1 = t1 * sn + t2 * cs;
    __nv_bfloat16 h0 = __float2bfloat16(v0), h1 = __float2bfloat16(v1);
    __nv_bfloat16 l0 = __float2bfloat16(v0 - __bfloat162float(h0));
    __nv_bfloat16 l1 = __float2bfloat16(v1 - __bfloat162float(h1));
    size_t r = ((size_t)row * NKV + kh) * 256;
    out[r + d] = h0;       out[r + d + 64] = h1;
    out[r + 128 + d] = l0; out[r + 192 + d] = l1;
}

// qkv[row][2560 + kh*128 + d] -> vs2[(row*NKV+kh)][256] = [vh | vl]
__global__ void split_v2_kernel(const float* __restrict__ qkv, __nv_bfloat16* __restrict__ out) {
    int i = blockIdx.x * 256 + threadIdx.x;          // < MROWS*KCOLS
    int c = i & 511, brow = i >> 9;
    int kh = c >> 7, d = c & 127;
    float x = qkv[(size_t)brow * QKVCOLS + QCOLS + KCOLS + kh * HD + d];
    __nv_bfloat16 hi = __float2bfloat16(x);
    __nv_bfloat16 lo = __float2bfloat16(x - __bfloat162float(hi));
    size_t r = ((size_t)brow * NKV + kh) * 256;
    out[r + d] = hi; out[r + 128 + d] = lo;
}

// ---------------------------------------------------------------------------
// bf16 mma.sync GEMM (unchanged from R8): CTA 128x256, warp 64x64, 3 stages.
// ---------------------------------------------------------------------------
#define BK_G 64
#define NCHUNK (K3 / BK_G)                 // 96
#define ASTG (128 * BK_G * 2)              // 16384
#define BSTG (256 * BK_G * 2)              // 32768
#define STAGE_BYTES (ASTG + BSTG)          // 49152
#define NSTAGE 3
#define GEMM_SMEM (NSTAGE * STAGE_BYTES)   // 147456

__global__ __launch_bounds__(256, 1)
void gemm3bf16_kernel(const __nv_bfloat16* __restrict__ A,
                      const __nv_bfloat16* __restrict__ Bt,
                      float* __restrict__ C, int Ntot) {
    extern __shared__ char smem[];
    const uint32_t sb = smem_to_u32(smem);
    const int tid  = threadIdx.x;
    const int lane = tid & 31;
    const int wid  = tid >> 5;
    const int wm = wid >> 2;
    const int wn = wid & 3;
    const int row0 = blockIdx.y * 128;
    const int col0 = blockIdx.x * 256;

    uint32_t sa[NSTAGE], sbf[NSTAGE];
#pragma unroll
    for (int s = 0; s < NSTAGE; s++) {
        sa[s]  = sb + s * STAGE_BYTES;
        sbf[s] = sb + s * STAGE_BYTES + ASTG;
    }

    float acc[4][8][4];
#pragma unroll
    for (int i = 0; i < 4; i++)
#pragma unroll
        for (int j = 0; j < 8; j++)
#pragma unroll
            for (int r = 0; r < 4; r++) acc[i][j][r] = 0.0f;

    const char* Abase = (const char*)A;
    const char* Bbase = (const char*)Bt;

    auto load_stage = [&](int kc, int s) {
#pragma unroll
        for (int it = 0; it < 12; it++) {
            int seg = tid + it * 256;
            int isA = seg < 1024;
            int s2 = isA ? seg : seg - 1024;
            int r = s2 >> 3, ch = s2 & 7;
            const char* g = (isA ? Abase : Bbase)
                + (size_t)((isA ? row0 : col0) + r) * (K3 * 2) + (size_t)kc * 128 + ch * 16;
            uint32_t saddr = (isA ? sa[s] : sbf[s]) + SWZ128(r * 128 + ch * 16);
            cp_async16(saddr, g);
        }
    };

    load_stage(0, 0);
    asm volatile("cp.async.commit_group;" ::: "memory");
    load_stage(1, 1);
    asm volatile("cp.async.commit_group;" ::: "memory");

    const int sub = lane >> 3;
    const int l7  = lane & 7;

    int sidx = 0;
    for (int c = 0; c < NCHUNK; c++) {
        asm volatile("cp.async.wait_group 1;" ::: "memory");
        __syncthreads();

        if (c + 2 < NCHUNK) {
            int ns = sidx + 2;
            if (ns >= NSTAGE) ns -= NSTAGE;
            load_stage(c + 2, ns);
        }
        asm volatile("cp.async.commit_group;" ::: "memory");

        const uint32_t ab = sa[sidx];
        const uint32_t bb = sbf[sidx];

#pragma unroll
        for (int ks = 0; ks < 4; ks++) {
            uint32_t afr[4][4];
#pragma unroll
            for (int im = 0; im < 4; im++) {
                int r = wm * 64 + im * 16 + (sub & 1) * 8 + l7;
                int cc = ks * 16 + (sub >> 1) * 8;
                ldsm_x4(afr[im], ab + SWZ128(r * 128 + cc * 2));
            }
            uint32_t bfr[4][4];
#pragma unroll
            for (int g = 0; g < 4; g++) {
                int r = wn * 64 + g * 16 + (sub >> 1) * 8 + l7;
                int cc = ks * 16 + (sub & 1) * 8;
                ldsm_x4(bfr[g], bb + SWZ128(r * 128 + cc * 2));
            }
#pragma unroll
            for (int im = 0; im < 4; im++)
#pragma unroll
                for (int in = 0; in < 8; in++)
                    mma16816(acc[im][in], afr[im], &bfr[in >> 1][(in & 1) * 2]);
        }

        if (++sidx == NSTAGE) sidx = 0;
    }

    const int gid = lane >> 2;
    const int tig = lane & 3;
#pragma unroll
    for (int im = 0; im < 4; im++) {
#pragma unroll
        for (int in = 0; in < 8; in++) {
            int r = row0 + wm * 64 + im * 16 + gid;
            int cc = col0 + wn * 64 + in * 8 + 2 * tig;
            float2* p0 = (float2*)(C + (size_t)r * Ntot + cc);
            float2* p1 = (float2*)(C + (size_t)(r + 8) * Ntot + cc);
            *p0 = make_float2(acc[im][in][0], acc[im][in][1]);
            *p1 = make_float2(acc[im][in][2], acc[im][in][3]);
        }
    }
}

// ---------------------------------------------------------------------------
// Flash attention v2: CTA = (qtile 128 positions, head, batch). 8 warps.
// Q = [qh|ql] (4 panels of 64 cols), K = [kh|kl], V = [vh|vl].
// Scores: 3 panel-pairings (qh,kh) (ql,kh) (qh,kl) — exact 3-term split.
// smem: Q 64KB + 2 x (K 32KB + V 32KB) = 192KB.
// ---------------------------------------------------------------------------
#define FA_SMEM 196608

__global__ __launch_bounds__(256, 1)
void flash_attn_kernel(const __nv_bfloat16* __restrict__ qs2,
                       const __nv_bfloat16* __restrict__ ks2,
                       const __nv_bfloat16* __restrict__ vs2,
                       __nv_bfloat16* __restrict__ atts) {
    extern __shared__ char smem[];
    const uint32_t sbase = smem_to_u32(smem);
    const int tid = threadIdx.x;
    const int lane = tid & 31;
    const int w = tid >> 5;                 // 0..7 -> q rows w*16..w*16+15
    const int sub = lane >> 3, l7 = lane & 7;
    const int gid = lane >> 2, tig = lane & 3;

    const int qt = blockIdx.x;              // 0..15
    const int h  = blockIdx.y;
    const int b  = blockIdx.z;
    const int kh = h >> 2;
    const int i0 = qt * 128;
    int jt0 = 2 * qt - 8; if (jt0 < 0) jt0 = 0;
    const int nt = 2 * qt + 2 - jt0;        // 2..10 key tiles of 64
    const int j0 = jt0 * 64;

    const uint32_t QS  = sbase;                      // 4 panels x 16384
    const uint32_t KS0 = sbase + 65536u;             // + s*32768, panels x 8192
    const uint32_t VS0 = sbase + 131072u;            // + s*32768, panels x 8192

    // ---- load Q tile: 128 rows x 256 cols ----
    {
        const char* qb = (const char*)(qs2 + ((size_t)(b * SEQ + i0) * NH + h) * 256);
#pragma unroll
        for (int it = 0; it < 16; it++) {
            int idx = tid + it * 256;               // 0..4095
            int r = idx >> 5, ch = idx & 31;
            cp_async16(QS + (ch >> 3) * 16384 + SWZ128(r * 128 + (ch & 7) * 16),
                       qb + (size_t)r * (NH * 256 * 2) + ch * 16);
        }
    }
    auto load_kv = [&](int t, int s) {
        int jb = j0 + t * 64;
        const char* kb = (const char*)(ks2 + ((size_t)(b * SEQ + jb) * NKV + kh) * 256);
        const char* vb = (const char*)(vs2 + ((size_t)(b * SEQ + jb) * NKV + kh) * 256);
        uint32_t ksb = KS0 + (uint32_t)s * 32768u;
        uint32_t vsb = VS0 + (uint32_t)s * 32768u;
#pragma unroll
        for (int it = 0; it < 16; it++) {
            int idx = tid + it * 256;               // 0..4095
            if (idx < 2048) {
                int r = idx >> 5, ch = idx & 31;
                cp_async16(ksb + (ch >> 3) * 8192 + SWZ128(r * 128 + (ch & 7) * 16),
                           kb + (size_t)r * (NKV * 256 * 2) + ch * 16);
            } else {
                int i2 = idx - 2048;
                int r = i2 >> 5, ch = i2 & 31;
                cp_async16(vsb + (ch >> 3) * 8192 + SWZ128(r * 128 + (ch & 7) * 16),
                           vb + (size_t)r * (NKV * 256 * 2) + ch * 16);
            }
        }
    };

    load_kv(0, 0);
    asm volatile("cp.async.commit_group;" ::: "memory");   // group0: Q + K/V tile0
    load_kv(1, 1);
    asm volatile("cp.async.commit_group;" ::: "memory");   // nt>=2 always

    float o[16][4];
#pragma unroll
    for (int i = 0; i < 16; i++)
#pragma unroll
        for (int e = 0; e < 4; e++) o[i][e] = 0.0f;
    float l0 = 0.0f, l1 = 0.0f;

    const float SCL2E = 0.08838834764831845f * 1.4426950408889634f;
    const int irow0 = i0 + w * 16 + gid;

    for (int t = 0; t < nt; t++) {
        if (t + 1 < nt) { asm volatile("cp.async.wait_group 1;" ::: "memory"); }
        else            { asm volatile("cp.async.wait_group 0;" ::: "memory"); }
        __syncthreads();

        const uint32_t ks_ = KS0 + (uint32_t)(t & 1) * 32768u;
        const uint32_t vs_ = VS0 + (uint32_t)(t & 1) * 32768u;

        // ---- scores: 3 pairings x 8 k16-steps ----
        float s[8][4];
#pragma unroll
        for (int nb = 0; nb < 8; nb++)
#pragma unroll
            for (int e = 0; e < 4; e++) s[nb][e] = 0.0f;

#pragma unroll
        for (int pr = 0; pr < 3; pr++) {
            const int qb0 = (pr == 1) ? 2 : 0;       // ql for pairing 1
            const int kb0 = (pr == 2) ? 2 : 0;       // kl for pairing 2
#pragma unroll
            for (int st = 0; st < 8; st++) {
                int pq = qb0 + (st >> 2);
                int pk = kb0 + (st >> 2);
                int coff = (st & 3) * 16;
                uint32_t af[4];
                ldsm_x4(af, QS + pq * 16384 +
                        SWZ128((w * 16 + (sub & 1) * 8 + l7) * 128 + (coff + (sub >> 1) * 8) * 2));
                uint32_t bfr[4][4];
#pragma unroll
                for (int g = 0; g < 4; g++)
                    ldsm_x4(bfr[g], ks_ + pk * 8192 +
                            SWZ128((g * 16 + (sub >> 1) * 8 + l7) * 128 + (coff + (sub & 1) * 8) * 2));
#pragma unroll
                for (int nb = 0; nb < 8; nb++)
                    mma16816(s[nb], af, &bfr[nb >> 1][(nb & 1) * 2]);
            }
        }

        // ---- mask + exp (max-free), row sums ----
        const int jb = j0 + t * 64;
        float part0 = 0.0f, part1 = 0.0f;
#pragma unroll
        for (int nb = 0; nb < 8; nb++) {
            int jc = jb + nb * 8 + 2 * tig;
#pragma unroll
            for (int e = 0; e < 4; e++) {
                int j = jc + (e & 1);
                int i = irow0 + (e >> 1) * 8;
                bool ok = (j <= i) && (i - j < WIN);
                float p = ok ? exp2f(s[nb][e] * SCL2E) : 0.0f;
                s[nb][e] = p;
            }
            part0 += s[nb][0] + s[nb][1];
            part1 += s[nb][2] + s[nb][3];
        }
        part0 += __shfl_xor_sync(0xffffffffu, part0, 1);
        part0 += __shfl_xor_sync(0xffffffffu, part0, 2);
        part1 += __shfl_xor_sync(0xffffffffu, part1, 1);
        part1 += __shfl_xor_sync(0xffffffffu, part1, 2);
        l0 += part0; l1 += part1;

        // ---- O += P @ Vtile (3-term split) ----
#pragma unroll
        for (int ks2i = 0; ks2i < 4; ks2i++) {
            uint32_t ah[4], al[4];
            {
                float x, y; __nv_bfloat16 hx, hy, lx, ly;
                x = s[2 * ks2i][0];     y = s[2 * ks2i][1];
                hx = __float2bfloat16(x); hy = __float2bfloat16(y);
                lx = __float2bfloat16(x - __bfloat162float(hx));
                ly = __float2bfloat16(y - __bfloat162float(hy));
                ah[0] = bfpack(hx, hy); al[0] = bfpack(lx, ly);
                x = s[2 * ks2i][2];     y = s[2 * ks2i][3];
                hx = __float2bfloat16(x); hy = __float2bfloat16(y);
                lx = __float2bfloat16(x - __bfloat162float(hx));
                ly = __float2bfloat16(y - __bfloat162float(hy));
                ah[1] = bfpack(hx, hy); al[1] = bfpack(lx, ly);
                x = s[2 * ks2i + 1][0]; y = s[2 * ks2i + 1][1];
                hx = __float2bfloat16(x); hy = __float2bfloat16(y);
                lx = __float2bfloat16(x - __bfloat162float(hx));
                ly = __float2bfloat16(y - __bfloat162float(hy));
                ah[2] = bfpack(hx, hy); al[2] = bfpack(lx, ly);
                x = s[2 * ks2i + 1][2]; y = s[2 * ks2i + 1][3];
                hx = __float2bfloat16(x); hy = __float2bfloat16(y);
                lx = __float2bfloat16(x - __bfloat162float(hx));
                ly = __float2bfloat16(y - __bfloat162float(hy));
                ah[3] = bfpack(hx, hy); al[3] = bfpack(lx, ly);
            }
#pragma unroll
            for (int g = 0; g < 8; g++) {
                uint32_t bh[4], bl[4];
                uint32_t off = SWZ128((ks2i * 16 + (sub & 1) * 8 + l7) * 128 +
                                      ((g & 3) * 16 + (sub >> 1) * 8) * 2);
                ldsm_x4_t(bh, vs_ + (g >> 2) * 8192 + off);
                ldsm_x4_t(bl, vs_ + 16384u + (g >> 2) * 8192 + off);
                mma16816(o[2 * g],     ah, &bh[0]);
                mma16816(o[2 * g + 1], ah, &bh[2]);
                mma16816(o[2 * g],     al, &bh[0]);
                mma16816(o[2 * g + 1], al, &bh[2]);
                mma16816(o[2 * g],     ah, &bl[0]);
                mma16816(o[2 * g + 1], ah, &bl[2]);
            }
        }

        __syncthreads();
        if (t + 2 < nt) load_kv(t + 2, t & 1);
        asm volatile("cp.async.commit_group;" ::: "memory");
    }

    // ---- normalize + write split output ----
    const float linv0 = 1.0f / l0;
    const float linv1 = 1.0f / l1;
    const size_t row0 = (size_t)(b * SEQ) + irow0;
    const size_t row1 = row0 + 8;
#pragma unroll
    for (int nb = 0; nb < 16; nb++) {
        int c0 = h * 128 + nb * 8 + 2 * tig;
        float v0 = o[nb][0] * linv0, v1 = o[nb][1] * linv0;
        float v2 = o[nb][2] * linv1, v3 = o[nb][3] * linv1;
        __nv_bfloat16 h0 = __float2bfloat16(v0), h1 = __float2bfloat16(v1);
        __nv_bfloat16 h2 = __float2bfloat16(v2), h3 = __float2bfloat16(v3);
        __nv_bfloat16 e0 = __float2bfloat16(v0 - __bfloat162float(h0));
        __nv_bfloat16 e1 = __float2bfloat16(v1 - __bfloat162float(h1));
        __nv_bfloat16 e2 = __float2bfloat16(v2 - __bfloat162float(h2));
        __nv_bfloat16 e3 = __float2bfloat16(v3 - __bfloat162float(h3));
        uint32_t hi01 = bfpack(h0, h1), lo01 = bfpack(e0, e1);
        uint32_t hi23 = bfpack(h2, h3), lo23 = bfpack(e2, e3);
        *(uint32_t*)(atts + row0 * K3 + c0)        = hi01;
        *(uint32_t*)(atts + row0 * K3 + 2048 + c0) = lo01;
        *(uint32_t*)(atts + row0 * K3 + 4096 + c0) = hi01;
        *(uint32_t*)(atts + row1 * K3 + c0)        = hi23;
        *(uint32_t*)(atts + row1 * K3 + 2048 + c0) = lo23;
        *(uint32_t*)(atts + row1 * K3 + 4096 + c0) = hi23;
    }
}

// ---------------------------------------------------------------------------
// Launch
// ---------------------------------------------------------------------------
extern "C" void kernel_launch(void* const* d_in, const int* in_sizes, int n_in,
                              void* d_out, int out_size) {
    const float* x  = (const float*)d_in[0];
    const float* Wq = (const float*)d_in[1];
    const float* Wk = (const float*)d_in[2];
    const float* Wv = (const float*)d_in[3];
    const float* Wo = (const float*)d_in[4];
    float* out = (float*)d_out;

    float *qkv;
    __nv_bfloat16 *xs, *atts, *wqkvt, *wot, *qs2, *ks2, *vs2;
    cudaGetSymbolAddress((void**)&qkv,   g_qkv);
    cudaGetSymbolAddress((void**)&xs,    g_xs);
    cudaGetSymbolAddress((void**)&atts,  g_atts);
    cudaGetSymbolAddress((void**)&wqkvt, g_wqkvt);
    cudaGetSymbolAddress((void**)&wot,   g_wot);
    cudaGetSymbolAddress((void**)&qs2,   g_qs2);
    cudaGetSymbolAddress((void**)&ks2,   g_ks2);
    cudaGetSymbolAddress((void**)&vs2,   g_vs2);

    cudaFuncSetAttribute(gemm3bf16_kernel, cudaFuncAttributeMaxDynamicSharedMemorySize, GEMM_SMEM);
    cudaFuncSetAttribute(flash_attn_kernel, cudaFuncAttributeMaxDynamicSharedMemorySize, FA_SMEM);

    // 1) Split inputs/weights into 3-term bf16 ([Wq|Wk|Wv]^T fused)
    {
        int total = MROWS * EMB;
        splitrows_kernel<<<(total + 255) / 256, 256>>>(x, xs, total);
        dim3 tb(32, 32);
        splitw_kernel<<<dim3(QCOLS / 32, EMB / 32), tb>>>(Wq, wqkvt, QCOLS);
        splitw_kernel<<<dim3(KCOLS / 32, EMB / 32), tb>>>(Wk, wqkvt + (size_t)QCOLS * K3, KCOLS);
        splitw_kernel<<<dim3(KCOLS / 32, EMB / 32), tb>>>(Wv, wqkvt + (size_t)(QCOLS + KCOLS) * K3, KCOLS);
        splitw_kernel<<<dim3(EMB / 32, QCOLS / 32), tb>>>(Wo, wot, EMB);
    }

    // 2) Fused QKV projection (tensor cores), C = [q|k|v] fp32
    gemm3bf16_kernel<<<dim3(QKVCOLS / 256, MROWS / 128), 256, GEMM_SMEM>>>(xs, wqkvt, qkv, QKVCOLS);

    // 3) Fused RoPE + split into flash-attention layouts
    rope_split_q_kernel<<<(MROWS * NH * 64) / 256, 256>>>(qkv, qs2);
    rope_split_k_kernel<<<(MROWS * NKV * 64) / 256, 256>>>(qkv, ks2);
    split_v2_kernel<<<(MROWS * KCOLS) / 256, 256>>>(qkv, vs2);

    // 4) Flash attention (writes split atts directly)
    flash_attn_kernel<<<dim3(SEQ / 128, NH, BATCH), 256, FA_SMEM>>>(qs2, ks2, vs2, atts);

    // 5) Output projection
    gemm3bf16_kernel<<<dim3(EMB / 256, MROWS / 128), 256, GEMM_SMEM>>>(atts, wot, out, EMB);
}

// round 14
// speedup vs baseline: 1.2598x; 1.0008x over previous
#include <cuda_runtime.h>
#include <cuda_bf16.h>
#include <cstdint>

// ---------------------------------------------------------------------------
// Problem constants
// ---------------------------------------------------------------------------
#define BATCH 2
#define SEQ   2048
#define EMB   2048
#define NH    16
#define NKV   4
#define HD    128
#define WIN   512
#define MROWS (BATCH * SEQ)          // 4096
#define QCOLS (NH * HD)              // 2048
#define KCOLS (NKV * HD)             // 512
#define QKVCOLS (QCOLS + 2 * KCOLS)  // 3072
#define K3    (3 * EMB)              // 6144  (3-term bf16 split along K)

// ---------------------------------------------------------------------------
// Scratch (static device memory; allocations are forbidden)
// ---------------------------------------------------------------------------
__device__ float g_qkv[(size_t)MROWS * QKVCOLS];       // fused q|k|v fp32

__device__ __nv_bfloat16 g_xs   [(size_t)MROWS * K3];      // [Ah | Al | Ah] of x
__device__ __nv_bfloat16 g_atts [(size_t)MROWS * K3];      // attention out, split
__device__ __nv_bfloat16 g_wqkvt[(size_t)QKVCOLS * K3];    // [Wq|Wk|Wv]^T split
__device__ __nv_bfloat16 g_wot  [(size_t)EMB * K3];        // Wo^T split

// per-(row,head) split arrays for flash attention
__device__ __nv_bfloat16 g_qs2[(size_t)MROWS * NH  * 256]; // [qh|ql]
__device__ __nv_bfloat16 g_ks2[(size_t)MROWS * NKV * 256]; // [kh|kl]
__device__ __nv_bfloat16 g_vs2[(size_t)MROWS * NKV * 256]; // [vh|vl]

// ---------------------------------------------------------------------------
// Helpers
// ---------------------------------------------------------------------------
__device__ __forceinline__ uint32_t smem_to_u32(const void* p) {
    uint32_t a;
    asm("{ .reg .u64 t; cvta.to.shared.u64 t, %1; cvt.u32.u64 %0, t; }" : "=r"(a) : "l"(p));
    return a;
}
#define SWZ128(off) ((off) ^ (((off) >> 3) & 0x70))

__device__ __forceinline__ void cp_async16(uint32_t s, const void* g) {
    asm volatile("cp.async.cg.shared.global [%0], [%1], 16;" :: "r"(s), "l"(g));
}
__device__ __forceinline__ void ldsm_x4(uint32_t* r, uint32_t addr) {
    asm volatile("ldmatrix.sync.aligned.m8n8.x4.shared.b16 {%0,%1,%2,%3}, [%4];"
                 : "=r"(r[0]), "=r"(r[1]), "=r"(r[2]), "=r"(r[3]) : "r"(addr));
}
__device__ __forceinline__ void ldsm_x4_t(uint32_t* r, uint32_t addr) {
    asm volatile("ldmatrix.sync.aligned.m8n8.x4.trans.shared.b16 {%0,%1,%2,%3}, [%4];"
                 : "=r"(r[0]), "=r"(r[1]), "=r"(r[2]), "=r"(r[3]) : "r"(addr));
}
__device__ __forceinline__ void mma16816(float* d, const uint32_t* a, const uint32_t* b) {
    asm volatile("mma.sync.aligned.m16n8k16.row.col.f32.bf16.bf16.f32 "
                 "{%0,%1,%2,%3}, {%4,%5,%6,%7}, {%8,%9}, {%0,%1,%2,%3};"
                 : "+f"(d[0]), "+f"(d[1]), "+f"(d[2]), "+f"(d[3])
                 : "r"(a[0]), "r"(a[1]), "r"(a[2]), "r"(a[3]), "r"(b[0]), "r"(b[1]));
}
__device__ __forceinline__ uint32_t bfpack(__nv_bfloat16 a, __nv_bfloat16 b) {
    __nv_bfloat162 t(a, b);
    return *reinterpret_cast<uint32_t*>(&t);
}

// ---------------------------------------------------------------------------
// Split kernels
// ---------------------------------------------------------------------------
__global__ void splitrows_kernel(const float* __restrict__ A, __nv_bfloat16* __restrict__ out,
                                 int total) {
    int i = blockIdx.x * 256 + threadIdx.x;
    if (i >= total) return;
    int row = i >> 11;
    int k = i & 2047;
    float v = A[i];
    __nv_bfloat16 hi = __float2bfloat16(v);
    __nv_bfloat16 lo = __float2bfloat16(v - __bfloat162float(hi));
    size_t b = (size_t)row * K3 + k;
    out[b] = hi;
    out[b + EMB] = lo;
    out[b + 2 * EMB] = hi;
}

__global__ void splitw_kernel(const float* __restrict__ W, __nv_bfloat16* __restrict__ out, int N) {
    __shared__ float t[32][33];
    int n0 = blockIdx.x * 32, k0 = blockIdx.y * 32;
    int tx = threadIdx.x, ty = threadIdx.y;
    t[ty][tx] = W[(size_t)(k0 + ty) * N + n0 + tx];
    __syncthreads();
    float v = t[tx][ty];
    __nv_bfloat16 hi = __float2bfloat16(v);
    __nv_bfloat16 lo = __float2bfloat16(v - __bfloat162float(hi));
    size_t b = (size_t)(n0 + ty) * K3 + k0 + tx;
    out[b] = hi;
    out[b + EMB] = hi;
    out[b + 2 * EMB] = lo;
}

// qkv[row][h*128 + d] -> rope -> qs2[(row*NH+h)][256] = [qh | ql]
__global__ void rope_split_q_kernel(const float* __restrict__ qkv, __nv_bfloat16* __restrict__ out) {
    int idx = blockIdx.x * 256 + threadIdx.x;        // < MROWS*NH*64
    int d = idx & 63;
    int h = (idx >> 6) & (NH - 1);
    int row = idx >> 10;
    int pos = row & (SEQ - 1);
    float inv = __expf(-(float)d * (9.210340371976184f / 64.0f));
    float ang = (float)pos * inv;
    float sn, cs;
    sincosf(ang, &sn, &cs);
    const float* base = qkv + (size_t)row * QKVCOLS + h * HD;
    float t1 = base[d], t2 = base[d + 64];
    float v0 = t1 * cs - t2 * sn;
    float v1 = t1 * sn + t2 * cs;
    __nv_bfloat16 h0 = __float2bfloat16(v0), h1 = __float2bfloat16(v1);
    __nv_bfloat16 l0 = __float2bfloat16(v0 - __bfloat162float(h0));
    __nv_bfloat16 l1 = __float2bfloat16(v1 - __bfloat162float(h1));
    size_t r = ((size_t)row * NH + h) * 256;
    out[r + d] = h0;       out[r + d + 64] = h1;
    out[r + 128 + d] = l0; out[r + 192 + d] = l1;
}

// qkv[row][2048 + kh*128 + d] -> rope -> ks2[(row*NKV+kh)][256] = [kh | kl]
__global__ void rope_split_k_kernel(const float* __restrict__ qkv, __nv_bfloat16* __restrict__ out) {
    int idx = blockIdx.x * 256 + threadIdx.x;        // < MROWS*NKV*64
    int d = idx & 63;
    int kh = (idx >> 6) & (NKV - 1);
    int row = idx >> 8;
    int pos = row & (SEQ - 1);
    float inv = __expf(-(float)d * (9.210340371976184f / 64.0f));
    float ang = (float)pos * inv;
    float sn, cs;
    sincosf(ang, &sn, &cs);
    const float* base = qkv + (size_t)row * QKVCOLS + QCOLS + kh * HD;
    float t1 = base[d], t2 = base[d + 64];
    float v0 = t1 * cs - t2 * sn;
    float v1 = t1 * sn + t2 * cs;
    __nv_bfloat16 h0 = __float2bfloat16(v0), h1 = __float2bfloat16(v1);
    __nv_bfloat16 l0 = __float2bfloat16(v0 - __bfloat162float(h0));
    __nv_bfloat16 l1 = __float2bfloat16(v1 - __bfloat162float(h1));
    size_t r = ((size_t)row * NKV + kh) * 256;
    out[r + d] = h0;       out[r + d + 64] = h1;
    out[r + 128 + d] = l0; out[r + 192 + d] = l1;
}

// qkv[row][2560 + kh*128 + d] -> vs2[(row*NKV+kh)][256] = [vh | vl]
__global__ void split_v2_kernel(const float* __restrict__ qkv, __nv_bfloat16* __restrict__ out) {
    int i = blockIdx.x * 256 + threadIdx.x;          // < MROWS*KCOLS
    int c = i & 511, brow = i >> 9;
    int kh = c >> 7, d = c & 127;
    float x = qkv[(size_t)brow * QKVCOLS + QCOLS + KCOLS + kh * HD + d];
    __nv_bfloat16 hi = __float2bfloat16(x);
    __nv_bfloat16 lo = __float2bfloat16(x - __bfloat162float(hi));
    size_t r = ((size_t)brow * NKV + kh) * 256;
    out[r + d] = hi; out[r + 128 + d] = lo;
}

// ---------------------------------------------------------------------------
// bf16 mma.sync GEMM (unchanged from R8): CTA 128x256, warp 64x64, 3 stages.
// ---------------------------------------------------------------------------
#define BK_G 64
#define NCHUNK (K3 / BK_G)                 // 96
#define ASTG (128 * BK_G * 2)              // 16384
#define BSTG (256 * BK_G * 2)              // 32768
#define STAGE_BYTES (ASTG + BSTG)          // 49152
#define NSTAGE 3
#define GEMM_SMEM (NSTAGE * STAGE_BYTES)   // 147456

__global__ __launch_bounds__(256, 1)
void gemm3bf16_kernel(const __nv_bfloat16* __restrict__ A,
                      const __nv_bfloat16* __restrict__ Bt,
                      float* __restrict__ C, int Ntot) {
    extern __shared__ char smem[];
    const uint32_t sb = smem_to_u32(smem);
    const int tid  = threadIdx.x;
    const int lane = tid & 31;
    const int wid  = tid >> 5;
    const int wm = wid >> 2;
    const int wn = wid & 3;
    const int row0 = blockIdx.y * 128;
    const int col0 = blockIdx.x * 256;

    uint32_t sa[NSTAGE], sbf[NSTAGE];
#pragma unroll
    for (int s = 0; s < NSTAGE; s++) {
        sa[s]  = sb + s * STAGE_BYTES;
        sbf[s] = sb + s * STAGE_BYTES + ASTG;
    }

    float acc[4][8][4];
#pragma unroll
    for (int i = 0; i < 4; i++)
#pragma unroll
        for (int j = 0; j < 8; j++)
#pragma unroll
            for (int r = 0; r < 4; r++) acc[i][j][r] = 0.0f;

    const char* Abase = (const char*)A;
    const char* Bbase = (const char*)Bt;

    auto load_stage = [&](int kc, int s) {
#pragma unroll
        for (int it = 0; it < 12; it++) {
            int seg = tid + it * 256;
            int isA = seg < 1024;
            int s2 = isA ? seg : seg - 1024;
            int r = s2 >> 3, ch = s2 & 7;
            const char* g = (isA ? Abase : Bbase)
                + (size_t)((isA ? row0 : col0) + r) * (K3 * 2) + (size_t)kc * 128 + ch * 16;
            uint32_t saddr = (isA ? sa[s] : sbf[s]) + SWZ128(r * 128 + ch * 16);
            cp_async16(saddr, g);
        }
    };

    load_stage(0, 0);
    asm volatile("cp.async.commit_group;" ::: "memory");
    load_stage(1, 1);
    asm volatile("cp.async.commit_group;" ::: "memory");

    const int sub = lane >> 3;
    const int l7  = lane & 7;

    int sidx = 0;
    for (int c = 0; c < NCHUNK; c++) {
        asm volatile("cp.async.wait_group 1;" ::: "memory");
        __syncthreads();

        if (c + 2 < NCHUNK) {
            int ns = sidx + 2;
            if (ns >= NSTAGE) ns -= NSTAGE;
            load_stage(c + 2, ns);
        }
        asm volatile("cp.async.commit_group;" ::: "memory");

        const uint32_t ab = sa[sidx];
        const uint32_t bb = sbf[sidx];

#pragma unroll
        for (int ks = 0; ks < 4; ks++) {
            uint32_t afr[4][4];
#pragma unroll
            for (int im = 0; im < 4; im++) {
                int r = wm * 64 + im * 16 + (sub & 1) * 8 + l7;
                int cc = ks * 16 + (sub >> 1) * 8;
                ldsm_x4(afr[im], ab + SWZ128(r * 128 + cc * 2));
            }
            uint32_t bfr[4][4];
#pragma unroll
            for (int g = 0; g < 4; g++) {
                int r = wn * 64 + g * 16 + (sub >> 1) * 8 + l7;
                int cc = ks * 16 + (sub & 1) * 8;
                ldsm_x4(bfr[g], bb + SWZ128(r * 128 + cc * 2));
            }
#pragma unroll
            for (int im = 0; im < 4; im++)
#pragma unroll
                for (int in = 0; in < 8; in++)
                    mma16816(acc[im][in], afr[im], &bfr[in >> 1][(in & 1) * 2]);
        }

        if (++sidx == NSTAGE) sidx = 0;
    }

    const int gid = lane >> 2;
    const int tig = lane & 3;
#pragma unroll
    for (int im = 0; im < 4; im++) {
#pragma unroll
        for (int in = 0; in < 8; in++) {
            int r = row0 + wm * 64 + im * 16 + gid;
            int cc = col0 + wn * 64 + in * 8 + 2 * tig;
            float2* p0 = (float2*)(C + (size_t)r * Ntot + cc);
            float2* p1 = (float2*)(C + (size_t)(r + 8) * Ntot + cc);
            *p0 = make_float2(acc[im][in][0], acc[im][in][1]);
            *p1 = make_float2(acc[im][in][2], acc[im][in][3]);
        }
    }
}

// ---------------------------------------------------------------------------
// Flash attention v2: CTA = (qtile 128 positions, head, batch). 8 warps.
// Q = [qh|ql] (4 panels of 64 cols), K = [kh|kl], V = [vh|vl].
// Scores: 3 panel-pairings (qh,kh) (ql,kh) (qh,kl) — exact 3-term split.
// smem: Q 64KB + 2 x (K 32KB + V 32KB) = 192KB.
// ---------------------------------------------------------------------------
#define FA_SMEM 196608

__global__ __launch_bounds__(256, 1)
void flash_attn_kernel(const __nv_bfloat16* __restrict__ qs2,
                       const __nv_bfloat16* __restrict__ ks2,
                       const __nv_bfloat16* __restrict__ vs2,
                       __nv_bfloat16* __restrict__ atts) {
    extern __shared__ char smem[];
    const uint32_t sbase = smem_to_u32(smem);
    const int tid = threadIdx.x;
    const int lane = tid & 31;
    const int w = tid >> 5;                 // 0..7 -> q rows w*16..w*16+15
    const int sub = lane >> 3, l7 = lane & 7;
    const int gid = lane >> 2, tig = lane & 3;

    const int qt = blockIdx.x;              // 0..15
    const int h  = blockIdx.y;
    const int b  = blockIdx.z;
    const int kh = h >> 2;
    const int i0 = qt * 128;
    int jt0 = 2 * qt - 8; if (jt0 < 0) jt0 = 0;
    const int nt = 2 * qt + 2 - jt0;        // 2..10 key tiles of 64
    const int j0 = jt0 * 64;

    const uint32_t QS  = sbase;                      // 4 panels x 16384
    const uint32_t KS0 = sbase + 65536u;             // + s*32768, panels x 8192
    const uint32_t VS0 = sbase + 131072u;            // + s*32768, panels x 8192

    // ---- load Q tile: 128 rows x 256 cols ----
    {
        const char* qb = (const char*)(qs2 + ((size_t)(b * SEQ + i0) * NH + h) * 256);
#pragma unroll
        for (int it = 0; it < 16; it++) {
            int idx = tid + it * 256;               // 0..4095
            int r = idx >> 5, ch = idx & 31;
            cp_async16(QS + (ch >> 3) * 16384 + SWZ128(r * 128 + (ch & 7) * 16),
                       qb + (size_t)r * (NH * 256 * 2) + ch * 16);
        }
    }
    auto load_kv = [&](int t, int s) {
        int jb = j0 + t * 64;
        const char* kb = (const char*)(ks2 + ((size_t)(b * SEQ + jb) * NKV + kh) * 256);
        const char* vb = (const char*)(vs2 + ((size_t)(b * SEQ + jb) * NKV + kh) * 256);
        uint32_t ksb = KS0 + (uint32_t)s * 32768u;
        uint32_t vsb = VS0 + (uint32_t)s * 32768u;
#pragma unroll
        for (int it = 0; it < 16; it++) {
            int idx = tid + it * 256;               // 0..4095
            if (idx < 2048) {
                int r = idx >> 5, ch = idx & 31;
                cp_async16(ksb + (ch >> 3) * 8192 + SWZ128(r * 128 + (ch & 7) * 16),
                           kb + (size_t)r * (NKV * 256 * 2) + ch * 16);
            } else {
                int i2 = idx - 2048;
                int r = i2 >> 5, ch = i2 & 31;
                cp_async16(vsb + (ch >> 3) * 8192 + SWZ128(r * 128 + (ch & 7) * 16),
                           vb + (size_t)r * (NKV * 256 * 2) + ch * 16);
            }
        }
    };

    load_kv(0, 0);
    asm volatile("cp.async.commit_group;" ::: "memory");   // group0: Q + K/V tile0
    load_kv(1, 1);
    asm volatile("cp.async.commit_group;" ::: "memory");   // nt>=2 always

    float o[16][4];
#pragma unroll
    for (int i = 0; i < 16; i++)
#pragma unroll
        for (int e = 0; e < 4; e++) o[i][e] = 0.0f;
    float l0 = 0.0f, l1 = 0.0f;

    const float SCL2E = 0.08838834764831845f * 1.4426950408889634f;
    const int irow0 = i0 + w * 16 + gid;

    for (int t = 0; t < nt; t++) {
        if (t + 1 < nt) { asm volatile("cp.async.wait_group 1;" ::: "memory"); }
        else            { asm volatile("cp.async.wait_group 0;" ::: "memory"); }
        __syncthreads();

        const uint32_t ks_ = KS0 + (uint32_t)(t & 1) * 32768u;
        const uint32_t vs_ = VS0 + (uint32_t)(t & 1) * 32768u;

        // ---- scores: 3 pairings x 8 k16-steps ----
        float s[8][4];
#pragma unroll
        for (int nb = 0; nb < 8; nb++)
#pragma unroll
            for (int e = 0; e < 4; e++) s[nb][e] = 0.0f;

#pragma unroll
        for (int pr = 0; pr < 3; pr++) {
            const int qb0 = (pr == 1) ? 2 : 0;       // ql for pairing 1
            const int kb0 = (pr == 2) ? 2 : 0;       // kl for pairing 2
#pragma unroll
            for (int st = 0; st < 8; st++) {
                int pq = qb0 + (st >> 2);
                int pk = kb0 + (st >> 2);
                int coff = (st & 3) * 16;
                uint32_t af[4];
                ldsm_x4(af, QS + pq * 16384 +
                        SWZ128((w * 16 + (sub & 1) * 8 + l7) * 128 + (coff + (sub >> 1) * 8) * 2));
                uint32_t bfr[4][4];
#pragma unroll
                for (int g = 0; g < 4; g++)
                    ldsm_x4(bfr[g], ks_ + pk * 8192 +
                            SWZ128((g * 16 + (sub >> 1) * 8 + l7) * 128 + (coff + (sub & 1) * 8) * 2));
#pragma unroll
                for (int nb = 0; nb < 8; nb++)
                    mma16816(s[nb], af, &bfr[nb >> 1][(nb & 1) * 2]);
            }
        }

        // ---- mask + exp (max-free), row sums ----
        const int jb = j0 + t * 64;
        float part0 = 0.0f, part1 = 0.0f;
#pragma unroll
        for (int nb = 0; nb < 8; nb++) {
            int jc = jb + nb * 8 + 2 * tig;
#pragma unroll
            for (int e = 0; e < 4; e++) {
                int j = jc + (e & 1);
                int i = irow0 + (e >> 1) * 8;
                bool ok = (j <= i) && (i - j < WIN);
                float p = ok ? exp2f(s[nb][e] * SCL2E) : 0.0f;
                s[nb][e] = p;
            }
            part0 += s[nb][0] + s[nb][1];
            part1 += s[nb][2] + s[nb][3];
        }
        part0 += __shfl_xor_sync(0xffffffffu, part0, 1);
        part0 += __shfl_xor_sync(0xffffffffu, part0, 2);
        part1 += __shfl_xor_sync(0xffffffffu, part1, 1);
        part1 += __shfl_xor_sync(0xffffffffu, part1, 2);
        l0 += part0; l1 += part1;

        // ---- O += P @ Vtile (3-term split) ----
#pragma unroll
        for (int ks2i = 0; ks2i < 4; ks2i++) {
            uint32_t ah[4], al[4];
            {
                float x, y; __nv_bfloat16 hx, hy, lx, ly;
                x = s[2 * ks2i][0];     y = s[2 * ks2i][1];
                hx = __float2bfloat16(x); hy = __float2bfloat16(y);
                lx = __float2bfloat16(x - __bfloat162float(hx));
                ly = __float2bfloat16(y - __bfloat162float(hy));
                ah[0] = bfpack(hx, hy); al[0] = bfpack(lx, ly);
                x = s[2 * ks2i][2];     y = s[2 * ks2i][3];
                hx = __float2bfloat16(x); hy = __float2bfloat16(y);
                lx = __float2bfloat16(x - __bfloat162float(hx));
                ly = __float2bfloat16(y - __bfloat162float(hy));
                ah[1] = bfpack(hx, hy); al[1] = bfpack(lx, ly);
                x = s[2 * ks2i + 1][0]; y = s[2 * ks2i + 1][1];
                hx = __float2bfloat16(x); hy = __float2bfloat16(y);
                lx = __float2bfloat16(x - __bfloat162float(hx));
                ly = __float2bfloat16(y - __bfloat162float(hy));
                ah[2] = bfpack(hx, hy); al[2] = bfpack(lx, ly);
                x = s[2 * ks2i + 1][2]; y = s[2 * ks2i + 1][3];
                hx = __float2bfloat16(x); hy = __float2bfloat16(y);
                lx = __float2bfloat16(x - __bfloat162float(hx));
                ly = __float2bfloat16(y - __bfloat162float(hy));
                ah[3] = bfpack(hx, hy); al[3] = bfpack(lx, ly);
            }
#pragma unroll
            for (int g = 0; g < 8; g++) {
                uint32_t bh[4], bl[4];
                uint32_t off = SWZ128((ks2i * 16 + (sub & 1) * 8 + l7) * 128 +
                                      ((g & 3) * 16 + (sub >> 1) * 8) * 2);
                ldsm_x4_t(bh, vs_ + (g >> 2) * 8192 + off);
                ldsm_x4_t(bl, vs_ + 16384u + (g >> 2) * 8192 + off);
                mma16816(o[2 * g],     ah, &bh[0]);
                mma16816(o[2 * g + 1], ah, &bh[2]);
                mma16816(o[2 * g],     al, &bh[0]);
                mma16816(o[2 * g + 1], al, &bh[2]);
                mma16816(o[2 * g],     ah, &bl[0]);
                mma16816(o[2 * g + 1], ah, &bl[2]);
            }
        }

        __syncthreads();
        if (t + 2 < nt) load_kv(t + 2, t & 1);
        asm volatile("cp.async.commit_group;" ::: "memory");
    }

    // ---- normalize + write split output ----
    const float linv0 = 1.0f / l0;
    const float linv1 = 1.0f / l1;
    const size_t row0 = (size_t)(b * SEQ) + irow0;
    const size_t row1 = row0 + 8;
#pragma unroll
    for (int nb = 0; nb < 16; nb++) {
        int c0 = h * 128 + nb * 8 + 2 * tig;
        float v0 = o[nb][0] * linv0, v1 = o[nb][1] * linv0;
        float v2 = o[nb][2] * linv1, v3 = o[nb][3] * linv1;
        __nv_bfloat16 h0 = __float2bfloat16(v0), h1 = __float2bfloat16(v1);
        __nv_bfloat16 h2 = __float2bfloat16(v2), h3 = __float2bfloat16(v3);
        __nv_bfloat16 e0 = __float2bfloat16(v0 - __bfloat162float(h0));
        __nv_bfloat16 e1 = __float2bfloat16(v1 - __bfloat162float(h1));
        __nv_bfloat16 e2 = __float2bfloat16(v2 - __bfloat162float(h2));
        __nv_bfloat16 e3 = __float2bfloat16(v3 - __bfloat162float(h3));
        uint32_t hi01 = bfpack(h0, h1), lo01 = bfpack(e0, e1);
        uint32_t hi23 = bfpack(h2, h3), lo23 = bfpack(e2, e3);
        *(uint32_t*)(atts + row0 * K3 + c0)        = hi01;
        *(uint32_t*)(atts + row0 * K3 + 2048 + c0) = lo01;
        *(uint32_t*)(atts + row0 * K3 + 4096 + c0) = hi01;
        *(uint32_t*)(atts + row1 * K3 + c0)        = hi23;
        *(uint32_t*)(atts + row1 * K3 + 2048 + c0) = lo23;
        *(uint32_t*)(atts + row1 * K3 + 4096 + c0) = hi23;
    }
}

// ---------------------------------------------------------------------------
// Launch
// ---------------------------------------------------------------------------
extern "C" void kernel_launch(void* const* d_in, const int* in_sizes, int n_in,
                              void* d_out, int out_size) {
    const float* x  = (const float*)d_in[0];
    const float* Wq = (const float*)d_in[1];
    const float* Wk = (const float*)d_in[2];
    const float* Wv = (const float*)d_in[3];
    const float* Wo = (const float*)d_in[4];
    float* out = (float*)d_out;

    float *qkv;
    __nv_bfloat16 *xs, *atts, *wqkvt, *wot, *qs2, *ks2, *vs2;
    cudaGetSymbolAddress((void**)&qkv,   g_qkv);
    cudaGetSymbolAddress((void**)&xs,    g_xs);
    cudaGetSymbolAddress((void**)&atts,  g_atts);
    cudaGetSymbolAddress((void**)&wqkvt, g_wqkvt);
    cudaGetSymbolAddress((void**)&wot,   g_wot);
    cudaGetSymbolAddress((void**)&qs2,   g_qs2);
    cudaGetSymbolAddress((void**)&ks2,   g_ks2);
    cudaGetSymbolAddress((void**)&vs2,   g_vs2);

    cudaFuncSetAttribute(gemm3bf16_kernel, cudaFuncAttributeMaxDynamicSharedMemorySize, GEMM_SMEM);
    cudaFuncSetAttribute(flash_attn_kernel, cudaFuncAttributeMaxDynamicSharedMemorySize, FA_SMEM);

    // 1) Split inputs/weights into 3-term bf16 ([Wq|Wk|Wv]^T fused)
    {
        int total = MROWS * EMB;
        splitrows_kernel<<<(total + 255) / 256, 256>>>(x, xs, total);
        dim3 tb(32, 32);
        splitw_kernel<<<dim3(QCOLS / 32, EMB / 32), tb>>>(Wq, wqkvt, QCOLS);
        splitw_kernel<<<dim3(KCOLS / 32, EMB / 32), tb>>>(Wk, wqkvt + (size_t)QCOLS * K3, KCOLS);
        splitw_kernel<<<dim3(KCOLS / 32, EMB / 32), tb>>>(Wv, wqkvt + (size_t)(QCOLS + KCOLS) * K3, KCOLS);
        splitw_kernel<<<dim3(EMB / 32, QCOLS / 32), tb>>>(Wo, wot, EMB);
    }

    // 2) Fused QKV projection (tensor cores), C = [q|k|v] fp32
    gemm3bf16_kernel<<<dim3(QKVCOLS / 256, MROWS / 128), 256, GEMM_SMEM>>>(xs, wqkvt, qkv, QKVCOLS);

    // 3) Fused RoPE + split into flash-attention layouts
    rope_split_q_kernel<<<(MROWS * NH * 64) / 256, 256>>>(qkv, qs2);
    rope_split_k_kernel<<<(MROWS * NKV * 64) / 256, 256>>>(qkv, ks2);
    split_v2_kernel<<<(MROWS * KCOLS) / 256, 256>>>(qkv, vs2);

    // 4) Flash attention (writes split atts directly)
    flash_attn_kernel<<<dim3(SEQ / 128, NH, BATCH), 256, FA_SMEM>>>(qs2, ks2, vs2, atts);

    // 5) Output projection
    gemm3bf16_kernel<<<dim3(EMB / 256, MROWS / 128), 256, GEMM_SMEM>>>(atts, wot, out, EMB);
}